// round 1
// baseline (speedup 1.0000x reference)
#include <cuda_runtime.h>
#include <math.h>

// Shapes (fixed by the problem)
#define B   128
#define N   196
#define C   768
#define CTR 64
#define NM  (N*N)          // 38416

// Scratch (device globals: allocation-free rule)
__device__ float g_attn[B*CTR];
__device__ float g_xw[B*N*C];     // x @ proj_w^T   (77 MB)
__device__ float g_v[B*NM];       // attn @ v_c     (19.7 MB)

// ---------------------------------------------------------------------------
// K1: q = mean_N(x); attn = softmax( (q_hat . k_hat_c) * C^-0.5 )
// one block per batch
// ---------------------------------------------------------------------------
__global__ void attn_kernel(const float* __restrict__ x,
                            const float* __restrict__ k_c) {
    const int b = blockIdx.x;
    __shared__ float q[C];
    __shared__ float red[256];
    __shared__ float logits[CTR];
    const int tid = threadIdx.x;

    // mean over N (coalesced across channels)
    for (int c = tid; c < C; c += 256) {
        float s = 0.f;
        const float* xp = x + (size_t)b*N*C + c;
        #pragma unroll 4
        for (int n = 0; n < N; n++) s += xp[(size_t)n*C];
        q[c] = s * (1.0f/N);
    }
    __syncthreads();

    // ||q||
    float ps = 0.f;
    for (int c = tid; c < C; c += 256) ps += q[c]*q[c];
    red[tid] = ps;
    __syncthreads();
    for (int s = 128; s > 0; s >>= 1) {
        if (tid < s) red[tid] += red[tid+s];
        __syncthreads();
    }
    const float qinv = 1.0f / fmaxf(sqrtf(red[0]), 1e-12f);

    // per-warp centers: dot(q, k_col) and ||k_col||
    const int warp = tid >> 5, lane = tid & 31;
    for (int c = warp; c < CTR; c += 8) {
        float dot = 0.f, kn = 0.f;
        for (int k = lane; k < C; k += 32) {
            float kv = k_c[k*CTR + c];
            dot += q[k]*kv;
            kn  += kv*kv;
        }
        #pragma unroll
        for (int o = 16; o > 0; o >>= 1) {
            dot += __shfl_down_sync(0xffffffff, dot, o);
            kn  += __shfl_down_sync(0xffffffff, kn, o);
        }
        if (lane == 0) {
            float kinv = 1.0f / fmaxf(sqrtf(kn), 1e-12f);
            logits[c] = dot * qinv * kinv * 0.03608439182435161f; // 768^-0.5
        }
    }
    __syncthreads();

    if (tid == 0) {
        float mx = -1e30f;
        #pragma unroll
        for (int c = 0; c < CTR; c++) mx = fmaxf(mx, logits[c]);
        float sum = 0.f;
        #pragma unroll
        for (int c = 0; c < CTR; c++) { float e = expf(logits[c]-mx); logits[c] = e; sum += e; }
        float inv = 1.0f/sum;
        #pragma unroll
        for (int c = 0; c < CTR; c++) g_attn[b*CTR + c] = logits[c]*inv;
    }
}

// ---------------------------------------------------------------------------
// K2: v[b, nm] = sum_c attn[b,c] * v_c[c, nm]
// one thread per nm; v_c column cached in registers, reused for all 128 b
// ---------------------------------------------------------------------------
__global__ void mix_kernel(const float* __restrict__ v_c) {
    __shared__ float a_s[B*CTR];   // 32 KB
    const int tid = threadIdx.x;
    for (int i = tid; i < B*CTR; i += 256) a_s[i] = g_attn[i];
    __syncthreads();

    const int nm = blockIdx.x*256 + tid;
    if (nm >= NM) return;

    float vr[CTR];
    #pragma unroll
    for (int c = 0; c < CTR; c++) vr[c] = v_c[(size_t)c*NM + nm];

    for (int b = 0; b < B; b++) {
        const float* ap = a_s + b*CTR;
        float acc = 0.f;
        #pragma unroll
        for (int c = 0; c < CTR; c++) acc += ap[c]*vr[c];
        g_v[(size_t)b*NM + nm] = acc;
    }
}

// ---------------------------------------------------------------------------
// K3: xw = x @ proj_w^T     (M=25088, N=768, K=768)
// xw[m,n] = sum_k x[m,k] * W[n,k]
// 64x64x16 tiles, 256 threads, 4x4 micro-tile
// ---------------------------------------------------------------------------
#define BM 64
#define BN 64
#define BK 16

__global__ void gemm_xw(const float* __restrict__ X,
                        const float* __restrict__ W) {
    __shared__ float As[BK][BM];
    __shared__ float Bs[BK][BN];
    const int bm = blockIdx.y * BM;
    const int bn = blockIdx.x * BN;
    const int tid = threadIdx.x;
    const int tx = tid & 15, ty = tid >> 4;
    float acc[4][4] = {};

    for (int k0 = 0; k0 < C; k0 += BK) {
        #pragma unroll
        for (int i = 0; i < 4; i++) {
            int idx = tid + i*256;
            int m = idx >> 4, k = idx & 15;
            As[k][m] = X[(size_t)(bm+m)*C + k0 + k];
            int n2 = idx >> 4, k2 = idx & 15;
            Bs[k2][n2] = W[(size_t)(bn+n2)*C + k0 + k2];
        }
        __syncthreads();
        #pragma unroll
        for (int k = 0; k < BK; k++) {
            float a[4], bb[4];
            #pragma unroll
            for (int i = 0; i < 4; i++) a[i]  = As[k][ty*4+i];
            #pragma unroll
            for (int j = 0; j < 4; j++) bb[j] = Bs[k][tx*4+j];
            #pragma unroll
            for (int i = 0; i < 4; i++)
                #pragma unroll
                for (int j = 0; j < 4; j++) acc[i][j] += a[i]*bb[j];
        }
        __syncthreads();
    }
    #pragma unroll
    for (int i = 0; i < 4; i++)
        #pragma unroll
        for (int j = 0; j < 4; j++)
            g_xw[(size_t)(bm+ty*4+i)*C + bn + tx*4 + j] = acc[i][j];
}

// ---------------------------------------------------------------------------
// K4: out[b] = v[b] @ xw[b] + bias      (per batch: M=196, N=768, K=196)
// ---------------------------------------------------------------------------
__global__ void gemm_out(const float* __restrict__ bias,
                         float* __restrict__ OUT) {
    const int b = blockIdx.z;
    const float* A  = g_v  + (size_t)b*NM;      // (196,196)
    const float* Bm = g_xw + (size_t)b*N*C;     // (196,768)
    float* O = OUT + (size_t)b*N*C;

    __shared__ float As[BK][BM];
    __shared__ float Bs[BK][BN];
    const int bm = blockIdx.y * BM;
    const int bn = blockIdx.x * BN;
    const int tid = threadIdx.x;
    const int tx = tid & 15, ty = tid >> 4;
    float acc[4][4] = {};

    for (int k0 = 0; k0 < N; k0 += BK) {
        #pragma unroll
        for (int i = 0; i < 4; i++) {
            int idx = tid + i*256;
            // A tile: As[k][m] = A[(bm+m)*196 + k0+k], guard m and k
            int m = idx >> 4, k = idx & 15;
            float av = 0.f;
            if (bm + m < N && k0 + k < N) av = A[(size_t)(bm+m)*N + k0 + k];
            As[k][m] = av;
            // B tile: Bs[k][n] = Bm[(k0+k)*768 + bn+n], n-contiguous load
            int n2 = idx & 63, k2 = idx >> 6;
            float bv = 0.f;
            if (k0 + k2 < N) bv = Bm[(size_t)(k0+k2)*C + bn + n2];
            Bs[k2][n2] = bv;
        }
        __syncthreads();
        #pragma unroll
        for (int k = 0; k < BK; k++) {
            float a[4], bb[4];
            #pragma unroll
            for (int i = 0; i < 4; i++) a[i]  = As[k][ty*4+i];
            #pragma unroll
            for (int j = 0; j < 4; j++) bb[j] = Bs[k][tx*4+j];
            #pragma unroll
            for (int i = 0; i < 4; i++)
                #pragma unroll
                for (int j = 0; j < 4; j++) acc[i][j] += a[i]*bb[j];
        }
        __syncthreads();
    }
    #pragma unroll
    for (int i = 0; i < 4; i++) {
        int m = bm + ty*4 + i;
        if (m < N) {
            #pragma unroll
            for (int j = 0; j < 4; j++)
                O[(size_t)m*C + bn + tx*4 + j] = acc[i][j] + bias[bn + tx*4 + j];
        }
    }
}

// ---------------------------------------------------------------------------
extern "C" void kernel_launch(void* const* d_in, const int* in_sizes, int n_in,
                              void* d_out, int out_size) {
    const float* x      = (const float*)d_in[0];   // (128,196,768)
    const float* k_c    = (const float*)d_in[1];   // (768,64)
    const float* v_c    = (const float*)d_in[2];   // (64,196,196)
    const float* proj_w = (const float*)d_in[3];   // (768,768)
    const float* proj_b = (const float*)d_in[4];   // (768,)
    float* out = (float*)d_out;

    attn_kernel<<<B, 256>>>(x, k_c);
    mix_kernel<<<(NM + 255)/256, 256>>>(v_c);
    {
        dim3 grid(C/BN, (B*N)/BM);                 // (12, 392)
        gemm_xw<<<grid, 256>>>(x, proj_w);
    }
    {
        dim3 grid(C/BN, (N + BM - 1)/BM, B);       // (12, 4, 128)
        gemm_out<<<grid, 256>>>(proj_b, out);
    }
}

// round 2
// speedup vs baseline: 2.4350x; 2.4350x over previous
#include <cuda_runtime.h>
#include <math.h>

// Shapes (fixed by the problem)
#define B   128
#define N   196
#define C   768
#define CTR 64
#define NM  (N*N)          // 38416

// Scratch (device globals: allocation-free rule)
__device__ float g_attn[B*CTR];
__device__ float g_xw[B*N*C];     // x @ proj_w^T   (77 MB)
__device__ float g_v[B*NM];       // attn @ v_c     (19.7 MB)

// ---------------------------------------------------------------------------
// K1: q = mean_N(x); attn = softmax( (q_hat . k_hat_c) * C^-0.5 )
// ---------------------------------------------------------------------------
__global__ void attn_kernel(const float* __restrict__ x,
                            const float* __restrict__ k_c) {
    const int b = blockIdx.x;
    __shared__ float q[C];
    __shared__ float red[256];
    __shared__ float logits[CTR];
    const int tid = threadIdx.x;

    for (int c = tid; c < C; c += 256) {
        float s = 0.f;
        const float* xp = x + (size_t)b*N*C + c;
        #pragma unroll 4
        for (int n = 0; n < N; n++) s += xp[(size_t)n*C];
        q[c] = s * (1.0f/N);
    }
    __syncthreads();

    float ps = 0.f;
    for (int c = tid; c < C; c += 256) ps += q[c]*q[c];
    red[tid] = ps;
    __syncthreads();
    for (int s = 128; s > 0; s >>= 1) {
        if (tid < s) red[tid] += red[tid+s];
        __syncthreads();
    }
    const float qinv = 1.0f / fmaxf(sqrtf(red[0]), 1e-12f);

    const int warp = tid >> 5, lane = tid & 31;
    for (int c = warp; c < CTR; c += 8) {
        float dot = 0.f, kn = 0.f;
        for (int k = lane; k < C; k += 32) {
            float kv = k_c[k*CTR + c];
            dot += q[k]*kv;
            kn  += kv*kv;
        }
        #pragma unroll
        for (int o = 16; o > 0; o >>= 1) {
            dot += __shfl_down_sync(0xffffffff, dot, o);
            kn  += __shfl_down_sync(0xffffffff, kn, o);
        }
        if (lane == 0) {
            float kinv = 1.0f / fmaxf(sqrtf(kn), 1e-12f);
            logits[c] = dot * qinv * kinv * 0.03608439182435161f; // 768^-0.5
        }
    }
    __syncthreads();

    if (tid == 0) {
        float mx = -1e30f;
        #pragma unroll
        for (int c = 0; c < CTR; c++) mx = fmaxf(mx, logits[c]);
        float sum = 0.f;
        #pragma unroll
        for (int c = 0; c < CTR; c++) { float e = expf(logits[c]-mx); logits[c] = e; sum += e; }
        float inv = 1.0f/sum;
        #pragma unroll
        for (int c = 0; c < CTR; c++) g_attn[b*CTR + c] = logits[c]*inv;
    }
}

// ---------------------------------------------------------------------------
// K2: v[b, nm] = sum_c attn[b,c] * v_c[c, nm]
// ---------------------------------------------------------------------------
__global__ void mix_kernel(const float* __restrict__ v_c) {
    __shared__ float a_s[B*CTR];   // 32 KB
    const int tid = threadIdx.x;
    for (int i = tid; i < B*CTR; i += 256) a_s[i] = g_attn[i];
    __syncthreads();

    const int nm = blockIdx.x*256 + tid;
    if (nm >= NM) return;

    float vr[CTR];
    #pragma unroll
    for (int c = 0; c < CTR; c++) vr[c] = v_c[(size_t)c*NM + nm];

    for (int b = 0; b < B; b++) {
        const float* ap = a_s + b*CTR;
        float acc = 0.f;
        #pragma unroll
        for (int c = 0; c < CTR; c++) acc += ap[c]*vr[c];
        g_v[(size_t)b*NM + nm] = acc;
    }
}

// ---------------------------------------------------------------------------
// K3 (NEW): xw = x @ proj_w^T via tf32 mma.sync  (M=25088, N=768, K=768)
// Block tile 128x128x32, 8 warps, warp tile 64x32, mma m16n8k8.
// All dims divide evenly -> no guards.
// ---------------------------------------------------------------------------
#define XT_M 128
#define XT_N 128
#define XT_K 32

__device__ __forceinline__ unsigned f2tf32(float f) {
    unsigned r;
    asm("cvt.rna.tf32.f32 %0, %1;" : "=r"(r) : "f"(f));
    return r;
}

__global__ __launch_bounds__(256, 1)
void gemm_xw_tf32(const float* __restrict__ X,
                  const float* __restrict__ W) {
    // As[m][k] stride 36 -> frag-read banks (m*4+k)%32 all distinct
    __shared__ unsigned As[XT_M][XT_K + 4];   // 18.4 KB
    // Bs[k][n] stride 132 -> frag-read banks (k*4+n)%32 all distinct
    __shared__ unsigned Bs[XT_K][XT_N + 4];   // 17.4 KB

    const int tid  = threadIdx.x;
    const int lane = tid & 31;
    const int w    = tid >> 5;            // 0..7
    const int wm   = (w & 1) * 64;        // warp row offset in tile
    const int wn   = (w >> 1) * 32;       // warp col offset in tile
    const int bm   = blockIdx.y * XT_M;
    const int bn   = blockIdx.x * XT_N;

    const int ldrow = tid >> 3;           // 0..31
    const int ldk   = (tid & 7) * 4;      // 0,4,...,28

    const int gq = lane >> 2;             // groupID  0..7
    const int tq = lane & 3;              // thread-in-group 0..3

    float acc[4][4][4];
    #pragma unroll
    for (int i = 0; i < 4; i++)
        #pragma unroll
        for (int j = 0; j < 4; j++)
            #pragma unroll
            for (int r = 0; r < 4; r++) acc[i][j][r] = 0.f;

    float4 a_pre[4], b_pre[4];

    // ---- preload tile 0 ----
    #pragma unroll
    for (int i = 0; i < 4; i++) {
        a_pre[i] = *(const float4*)&X[(size_t)(bm + ldrow + 32*i)*C + ldk];
        b_pre[i] = *(const float4*)&W[(size_t)(bn + ldrow + 32*i)*C + ldk];
    }
    #pragma unroll
    for (int i = 0; i < 4; i++) {
        int r = ldrow + 32*i;
        As[r][ldk+0] = f2tf32(a_pre[i].x);
        As[r][ldk+1] = f2tf32(a_pre[i].y);
        As[r][ldk+2] = f2tf32(a_pre[i].z);
        As[r][ldk+3] = f2tf32(a_pre[i].w);
        Bs[ldk+0][r] = f2tf32(b_pre[i].x);
        Bs[ldk+1][r] = f2tf32(b_pre[i].y);
        Bs[ldk+2][r] = f2tf32(b_pre[i].z);
        Bs[ldk+3][r] = f2tf32(b_pre[i].w);
    }
    __syncthreads();

    const int NITER = C / XT_K;           // 24
    for (int it = 0; it < NITER; it++) {
        // prefetch next tile into registers (no sync needed)
        if (it + 1 < NITER) {
            int k0 = (it + 1) * XT_K;
            #pragma unroll
            for (int i = 0; i < 4; i++) {
                a_pre[i] = *(const float4*)&X[(size_t)(bm + ldrow + 32*i)*C + k0 + ldk];
                b_pre[i] = *(const float4*)&W[(size_t)(bn + ldrow + 32*i)*C + k0 + ldk];
            }
        }

        // compute 4 k-steps of 8
        #pragma unroll
        for (int ks = 0; ks < 4; ks++) {
            const int kb = ks * 8;
            unsigned af[4][4];
            #pragma unroll
            for (int mi = 0; mi < 4; mi++) {
                int r = wm + mi*16 + gq;
                af[mi][0] = As[r    ][kb + tq    ];
                af[mi][1] = As[r + 8][kb + tq    ];
                af[mi][2] = As[r    ][kb + tq + 4];
                af[mi][3] = As[r + 8][kb + tq + 4];
            }
            unsigned bf[4][2];
            #pragma unroll
            for (int nj = 0; nj < 4; nj++) {
                int cn = wn + nj*8 + gq;
                bf[nj][0] = Bs[kb + tq    ][cn];
                bf[nj][1] = Bs[kb + tq + 4][cn];
            }
            #pragma unroll
            for (int mi = 0; mi < 4; mi++)
                #pragma unroll
                for (int nj = 0; nj < 4; nj++) {
                    asm volatile(
                        "mma.sync.aligned.m16n8k8.row.col.f32.tf32.tf32.f32 "
                        "{%0,%1,%2,%3}, {%4,%5,%6,%7}, {%8,%9}, {%0,%1,%2,%3};"
                        : "+f"(acc[mi][nj][0]), "+f"(acc[mi][nj][1]),
                          "+f"(acc[mi][nj][2]), "+f"(acc[mi][nj][3])
                        : "r"(af[mi][0]), "r"(af[mi][1]), "r"(af[mi][2]), "r"(af[mi][3]),
                          "r"(bf[nj][0]), "r"(bf[nj][1]));
                }
        }
        __syncthreads();

        if (it + 1 < NITER) {
            #pragma unroll
            for (int i = 0; i < 4; i++) {
                int r = ldrow + 32*i;
                As[r][ldk+0] = f2tf32(a_pre[i].x);
                As[r][ldk+1] = f2tf32(a_pre[i].y);
                As[r][ldk+2] = f2tf32(a_pre[i].z);
                As[r][ldk+3] = f2tf32(a_pre[i].w);
                Bs[ldk+0][r] = f2tf32(b_pre[i].x);
                Bs[ldk+1][r] = f2tf32(b_pre[i].y);
                Bs[ldk+2][r] = f2tf32(b_pre[i].z);
                Bs[ldk+3][r] = f2tf32(b_pre[i].w);
            }
            __syncthreads();
        }
    }

    // ---- epilogue: c0,c1 at (row, 2*tq), c2,c3 at (row+8, 2*tq) ----
    #pragma unroll
    for (int mi = 0; mi < 4; mi++) {
        #pragma unroll
        for (int nj = 0; nj < 4; nj++) {
            int r  = bm + wm + mi*16 + gq;
            int cc = bn + wn + nj*8 + tq*2;
            float2 lo = make_float2(acc[mi][nj][0], acc[mi][nj][1]);
            float2 hi = make_float2(acc[mi][nj][2], acc[mi][nj][3]);
            *(float2*)&g_xw[(size_t)r*C + cc]       = lo;
            *(float2*)&g_xw[(size_t)(r+8)*C + cc]   = hi;
        }
    }
}

// ---------------------------------------------------------------------------
// K4: out[b] = v[b] @ xw[b] + bias      (per batch: M=196, N=768, K=196)
// (unchanged fp32 path — next round's target)
// ---------------------------------------------------------------------------
#define BM 64
#define BN 64
#define BK 16

__global__ void gemm_out(const float* __restrict__ bias,
                         float* __restrict__ OUT) {
    const int b = blockIdx.z;
    const float* A  = g_v  + (size_t)b*NM;      // (196,196)
    const float* Bm = g_xw + (size_t)b*N*C;     // (196,768)
    float* O = OUT + (size_t)b*N*C;

    __shared__ float As[BK][BM];
    __shared__ float Bs[BK][BN];
    const int bm = blockIdx.y * BM;
    const int bn = blockIdx.x * BN;
    const int tid = threadIdx.x;
    const int tx = tid & 15, ty = tid >> 4;
    float acc[4][4] = {};

    for (int k0 = 0; k0 < N; k0 += BK) {
        #pragma unroll
        for (int i = 0; i < 4; i++) {
            int idx = tid + i*256;
            int m = idx >> 4, k = idx & 15;
            float av = 0.f;
            if (bm + m < N && k0 + k < N) av = A[(size_t)(bm+m)*N + k0 + k];
            As[k][m] = av;
            int n2 = idx & 63, k2 = idx >> 6;
            float bv = 0.f;
            if (k0 + k2 < N) bv = Bm[(size_t)(k0+k2)*C + bn + n2];
            Bs[k2][n2] = bv;
        }
        __syncthreads();
        #pragma unroll
        for (int k = 0; k < BK; k++) {
            float a[4], bb[4];
            #pragma unroll
            for (int i = 0; i < 4; i++) a[i]  = As[k][ty*4+i];
            #pragma unroll
            for (int j = 0; j < 4; j++) bb[j] = Bs[k][tx*4+j];
            #pragma unroll
            for (int i = 0; i < 4; i++)
                #pragma unroll
                for (int j = 0; j < 4; j++) acc[i][j] += a[i]*bb[j];
        }
        __syncthreads();
    }
    #pragma unroll
    for (int i = 0; i < 4; i++) {
        int m = bm + ty*4 + i;
        if (m < N) {
            #pragma unroll
            for (int j = 0; j < 4; j++)
                O[(size_t)m*C + bn + tx*4 + j] = acc[i][j] + bias[bn + tx*4 + j];
        }
    }
}

// ---------------------------------------------------------------------------
extern "C" void kernel_launch(void* const* d_in, const int* in_sizes, int n_in,
                              void* d_out, int out_size) {
    const float* x      = (const float*)d_in[0];   // (128,196,768)
    const float* k_c    = (const float*)d_in[1];   // (768,64)
    const float* v_c    = (const float*)d_in[2];   // (64,196,196)
    const float* proj_w = (const float*)d_in[3];   // (768,768)
    const float* proj_b = (const float*)d_in[4];   // (768,)
    float* out = (float*)d_out;

    attn_kernel<<<B, 256>>>(x, k_c);
    mix_kernel<<<(NM + 255)/256, 256>>>(v_c);
    {
        dim3 grid(C/XT_N, (B*N)/XT_M);             // (6, 196)
        gemm_xw_tf32<<<grid, 256>>>(x, proj_w);
    }
    {
        dim3 grid(C/BN, (N + BM - 1)/BM, B);       // (12, 4, 128)
        gemm_out<<<grid, 256>>>(proj_b, out);
    }
}

// round 3
// speedup vs baseline: 3.6530x; 1.5002x over previous
#include <cuda_runtime.h>
#include <math.h>

// Shapes (fixed by the problem)
#define B   128
#define N   196
#define C   768
#define CTR 64
#define NM  (N*N)          // 38416

// Scratch (device globals: allocation-free rule)
__device__ float g_attn[B*CTR];
__device__ float g_xw[B*N*C];     // x @ proj_w^T   (77 MB)
__device__ float g_v[B*NM];       // attn @ v_c     (19.7 MB)

__device__ __forceinline__ unsigned f2tf32(float f) {
    unsigned r;
    asm("cvt.rna.tf32.f32 %0, %1;" : "=r"(r) : "f"(f));
    return r;
}

// ---------------------------------------------------------------------------
// K1: q = mean_N(x); attn = softmax( (q_hat . k_hat_c) * C^-0.5 )
// ---------------------------------------------------------------------------
__global__ void attn_kernel(const float* __restrict__ x,
                            const float* __restrict__ k_c) {
    const int b = blockIdx.x;
    __shared__ float q[C];
    __shared__ float red[256];
    __shared__ float logits[CTR];
    const int tid = threadIdx.x;

    for (int c = tid; c < C; c += 256) {
        float s = 0.f;
        const float* xp = x + (size_t)b*N*C + c;
        #pragma unroll 4
        for (int n = 0; n < N; n++) s += xp[(size_t)n*C];
        q[c] = s * (1.0f/N);
    }
    __syncthreads();

    float ps = 0.f;
    for (int c = tid; c < C; c += 256) ps += q[c]*q[c];
    red[tid] = ps;
    __syncthreads();
    for (int s = 128; s > 0; s >>= 1) {
        if (tid < s) red[tid] += red[tid+s];
        __syncthreads();
    }
    const float qinv = 1.0f / fmaxf(sqrtf(red[0]), 1e-12f);

    const int warp = tid >> 5, lane = tid & 31;
    for (int c = warp; c < CTR; c += 8) {
        float dot = 0.f, kn = 0.f;
        for (int k = lane; k < C; k += 32) {
            float kv = k_c[k*CTR + c];
            dot += q[k]*kv;
            kn  += kv*kv;
        }
        #pragma unroll
        for (int o = 16; o > 0; o >>= 1) {
            dot += __shfl_down_sync(0xffffffff, dot, o);
            kn  += __shfl_down_sync(0xffffffff, kn, o);
        }
        if (lane == 0) {
            float kinv = 1.0f / fmaxf(sqrtf(kn), 1e-12f);
            logits[c] = dot * qinv * kinv * 0.03608439182435161f; // 768^-0.5
        }
    }
    __syncthreads();

    if (tid == 0) {
        float mx = -1e30f;
        #pragma unroll
        for (int c = 0; c < CTR; c++) mx = fmaxf(mx, logits[c]);
        float sum = 0.f;
        #pragma unroll
        for (int c = 0; c < CTR; c++) { float e = expf(logits[c]-mx); logits[c] = e; sum += e; }
        float inv = 1.0f/sum;
        #pragma unroll
        for (int c = 0; c < CTR; c++) g_attn[b*CTR + c] = logits[c]*inv;
    }
}

// ---------------------------------------------------------------------------
// K2: v[b, nm] = sum_c attn[b,c] * v_c[c, nm]
// ---------------------------------------------------------------------------
__global__ void mix_kernel(const float* __restrict__ v_c) {
    __shared__ float a_s[B*CTR];   // 32 KB
    const int tid = threadIdx.x;
    for (int i = tid; i < B*CTR; i += 256) a_s[i] = g_attn[i];
    __syncthreads();

    const int nm = blockIdx.x*256 + tid;
    if (nm >= NM) return;

    float vr[CTR];
    #pragma unroll
    for (int c = 0; c < CTR; c++) vr[c] = v_c[(size_t)c*NM + nm];

    for (int b = 0; b < B; b++) {
        const float* ap = a_s + b*CTR;
        float acc = 0.f;
        #pragma unroll
        for (int c = 0; c < CTR; c++) acc += ap[c]*vr[c];
        g_v[(size_t)b*NM + nm] = acc;
    }
}

// ---------------------------------------------------------------------------
// K3: xw = x @ proj_w^T via tf32 mma.sync  (M=25088, N=768, K=768)
// Block tile 128x128x32, 8 warps, warp tile 64x32, mma m16n8k8.
// ---------------------------------------------------------------------------
#define XT_M 128
#define XT_N 128
#define XT_K 32

__global__ __launch_bounds__(256, 1)
void gemm_xw_tf32(const float* __restrict__ X,
                  const float* __restrict__ W) {
    __shared__ unsigned As[XT_M][XT_K + 4];
    __shared__ unsigned Bs[XT_K][XT_N + 4];

    const int tid  = threadIdx.x;
    const int lane = tid & 31;
    const int w    = tid >> 5;
    const int wm   = (w & 1) * 64;
    const int wn   = (w >> 1) * 32;
    const int bm   = blockIdx.y * XT_M;
    const int bn   = blockIdx.x * XT_N;

    const int ldrow = tid >> 3;
    const int ldk   = (tid & 7) * 4;

    const int gq = lane >> 2;
    const int tq = lane & 3;

    float acc[4][4][4];
    #pragma unroll
    for (int i = 0; i < 4; i++)
        #pragma unroll
        for (int j = 0; j < 4; j++)
            #pragma unroll
            for (int r = 0; r < 4; r++) acc[i][j][r] = 0.f;

    float4 a_pre[4], b_pre[4];

    #pragma unroll
    for (int i = 0; i < 4; i++) {
        a_pre[i] = *(const float4*)&X[(size_t)(bm + ldrow + 32*i)*C + ldk];
        b_pre[i] = *(const float4*)&W[(size_t)(bn + ldrow + 32*i)*C + ldk];
    }
    #pragma unroll
    for (int i = 0; i < 4; i++) {
        int r = ldrow + 32*i;
        As[r][ldk+0] = f2tf32(a_pre[i].x);
        As[r][ldk+1] = f2tf32(a_pre[i].y);
        As[r][ldk+2] = f2tf32(a_pre[i].z);
        As[r][ldk+3] = f2tf32(a_pre[i].w);
        Bs[ldk+0][r] = f2tf32(b_pre[i].x);
        Bs[ldk+1][r] = f2tf32(b_pre[i].y);
        Bs[ldk+2][r] = f2tf32(b_pre[i].z);
        Bs[ldk+3][r] = f2tf32(b_pre[i].w);
    }
    __syncthreads();

    const int NITER = C / XT_K;
    for (int it = 0; it < NITER; it++) {
        if (it + 1 < NITER) {
            int k0 = (it + 1) * XT_K;
            #pragma unroll
            for (int i = 0; i < 4; i++) {
                a_pre[i] = *(const float4*)&X[(size_t)(bm + ldrow + 32*i)*C + k0 + ldk];
                b_pre[i] = *(const float4*)&W[(size_t)(bn + ldrow + 32*i)*C + k0 + ldk];
            }
        }

        #pragma unroll
        for (int ks = 0; ks < 4; ks++) {
            const int kb = ks * 8;
            unsigned af[4][4];
            #pragma unroll
            for (int mi = 0; mi < 4; mi++) {
                int r = wm + mi*16 + gq;
                af[mi][0] = As[r    ][kb + tq    ];
                af[mi][1] = As[r + 8][kb + tq    ];
                af[mi][2] = As[r    ][kb + tq + 4];
                af[mi][3] = As[r + 8][kb + tq + 4];
            }
            unsigned bf[4][2];
            #pragma unroll
            for (int nj = 0; nj < 4; nj++) {
                int cn = wn + nj*8 + gq;
                bf[nj][0] = Bs[kb + tq    ][cn];
                bf[nj][1] = Bs[kb + tq + 4][cn];
            }
            #pragma unroll
            for (int mi = 0; mi < 4; mi++)
                #pragma unroll
                for (int nj = 0; nj < 4; nj++) {
                    asm volatile(
                        "mma.sync.aligned.m16n8k8.row.col.f32.tf32.tf32.f32 "
                        "{%0,%1,%2,%3}, {%4,%5,%6,%7}, {%8,%9}, {%0,%1,%2,%3};"
                        : "+f"(acc[mi][nj][0]), "+f"(acc[mi][nj][1]),
                          "+f"(acc[mi][nj][2]), "+f"(acc[mi][nj][3])
                        : "r"(af[mi][0]), "r"(af[mi][1]), "r"(af[mi][2]), "r"(af[mi][3]),
                          "r"(bf[nj][0]), "r"(bf[nj][1]));
                }
        }
        __syncthreads();

        if (it + 1 < NITER) {
            #pragma unroll
            for (int i = 0; i < 4; i++) {
                int r = ldrow + 32*i;
                As[r][ldk+0] = f2tf32(a_pre[i].x);
                As[r][ldk+1] = f2tf32(a_pre[i].y);
                As[r][ldk+2] = f2tf32(a_pre[i].z);
                As[r][ldk+3] = f2tf32(a_pre[i].w);
                Bs[ldk+0][r] = f2tf32(b_pre[i].x);
                Bs[ldk+1][r] = f2tf32(b_pre[i].y);
                Bs[ldk+2][r] = f2tf32(b_pre[i].z);
                Bs[ldk+3][r] = f2tf32(b_pre[i].w);
            }
            __syncthreads();
        }
    }

    #pragma unroll
    for (int mi = 0; mi < 4; mi++) {
        #pragma unroll
        for (int nj = 0; nj < 4; nj++) {
            int r  = bm + wm + mi*16 + gq;
            int cc = bn + wn + nj*8 + tq*2;
            float2 lo = make_float2(acc[mi][nj][0], acc[mi][nj][1]);
            float2 hi = make_float2(acc[mi][nj][2], acc[mi][nj][3]);
            *(float2*)&g_xw[(size_t)r*C + cc]       = lo;
            *(float2*)&g_xw[(size_t)(r+8)*C + cc]   = hi;
        }
    }
}

// ---------------------------------------------------------------------------
// K4 (NEW): out[b] = v[b] @ xw[b] + bias via tf32 mma.sync
// Per batch: M=196, N=768, K=196. Block tile 128x128x32, guards on M and K.
// A = g_v[b] (196x196 row-major), B = g_xw[b] (196x768 row-major, [k][n]).
// ---------------------------------------------------------------------------
__global__ __launch_bounds__(256, 1)
void gemm_out_tf32(const float* __restrict__ bias,
                   float* __restrict__ OUT) {
    __shared__ unsigned As[XT_M][XT_K + 4];   // [m][k]
    __shared__ unsigned Bs[XT_K][XT_N + 4];   // [k][n]

    const int b  = blockIdx.z;
    const float* A  = g_v  + (size_t)b*NM;     // (196,196)
    const float* Bm = g_xw + (size_t)b*N*C;    // (196,768)
    float* O = OUT + (size_t)b*N*C;

    const int tid  = threadIdx.x;
    const int lane = tid & 31;
    const int w    = tid >> 5;
    const int wm   = (w & 1) * 64;
    const int wn   = (w >> 1) * 32;
    const int bm   = blockIdx.y * XT_M;        // 0 or 128
    const int bn   = blockIdx.x * XT_N;        // 0..640

    // A loader: 128 rows x 32 k; thread -> (row = tid>>3 + 32*i, k = (tid&7)*4)
    const int a_row = tid >> 3;
    const int a_k   = (tid & 7) * 4;
    // B loader: 32 k-rows x 128 n; thread -> (k = tid>>3, n = (tid&7)*4 + 32*i)
    const int b_k   = tid >> 3;
    const int b_n   = (tid & 7) * 4;

    const int gq = lane >> 2;
    const int tq = lane & 3;

    float acc[4][4][4];
    #pragma unroll
    for (int i = 0; i < 4; i++)
        #pragma unroll
        for (int j = 0; j < 4; j++)
            #pragma unroll
            for (int r = 0; r < 4; r++) acc[i][j][r] = 0.f;

    const int NITER = (N + XT_K - 1) / XT_K;   // 7 (last tile k 192..223, valid to 195)
    for (int it = 0; it < NITER; it++) {
        const int k0 = it * XT_K;

        // load A tile (guard m<196 and k<196; 196%4==0 so float4 all-or-nothing)
        #pragma unroll
        for (int i = 0; i < 4; i++) {
            int m = a_row + 32*i;
            float4 v4 = make_float4(0.f,0.f,0.f,0.f);
            if (bm + m < N && k0 + a_k < N)
                v4 = *(const float4*)&A[(size_t)(bm+m)*N + k0 + a_k];
            As[m][a_k+0] = f2tf32(v4.x);
            As[m][a_k+1] = f2tf32(v4.y);
            As[m][a_k+2] = f2tf32(v4.z);
            As[m][a_k+3] = f2tf32(v4.w);
        }
        // load B tile (guard k<196; n always valid)
        {
            float4 v4 = make_float4(0.f,0.f,0.f,0.f);
            const bool kok = (k0 + b_k) < N;
            #pragma unroll
            for (int i = 0; i < 4; i++) {
                int n = b_n + 32*i;
                float4 t = kok ? *(const float4*)&Bm[(size_t)(k0+b_k)*C + bn + n] : v4;
                Bs[b_k][n+0] = f2tf32(t.x);
                Bs[b_k][n+1] = f2tf32(t.y);
                Bs[b_k][n+2] = f2tf32(t.z);
                Bs[b_k][n+3] = f2tf32(t.w);
            }
        }
        __syncthreads();

        #pragma unroll
        for (int ks = 0; ks < 4; ks++) {
            const int kb = ks * 8;
            unsigned af[4][4];
            #pragma unroll
            for (int mi = 0; mi < 4; mi++) {
                int r = wm + mi*16 + gq;
                af[mi][0] = As[r    ][kb + tq    ];
                af[mi][1] = As[r + 8][kb + tq    ];
                af[mi][2] = As[r    ][kb + tq + 4];
                af[mi][3] = As[r + 8][kb + tq + 4];
            }
            unsigned bf[4][2];
            #pragma unroll
            for (int nj = 0; nj < 4; nj++) {
                int cn = wn + nj*8 + gq;
                bf[nj][0] = Bs[kb + tq    ][cn];
                bf[nj][1] = Bs[kb + tq + 4][cn];
            }
            #pragma unroll
            for (int mi = 0; mi < 4; mi++)
                #pragma unroll
                for (int nj = 0; nj < 4; nj++) {
                    asm volatile(
                        "mma.sync.aligned.m16n8k8.row.col.f32.tf32.tf32.f32 "
                        "{%0,%1,%2,%3}, {%4,%5,%6,%7}, {%8,%9}, {%0,%1,%2,%3};"
                        : "+f"(acc[mi][nj][0]), "+f"(acc[mi][nj][1]),
                          "+f"(acc[mi][nj][2]), "+f"(acc[mi][nj][3])
                        : "r"(af[mi][0]), "r"(af[mi][1]), "r"(af[mi][2]), "r"(af[mi][3]),
                          "r"(bf[nj][0]), "r"(bf[nj][1]));
                }
        }
        __syncthreads();
    }

    // epilogue with bias; guard rows < 196
    #pragma unroll
    for (int mi = 0; mi < 4; mi++) {
        #pragma unroll
        for (int nj = 0; nj < 4; nj++) {
            int r  = bm + wm + mi*16 + gq;
            int cc = bn + wn + nj*8 + tq*2;
            float b0 = bias[cc], b1 = bias[cc+1];
            if (r < N) {
                float2 lo = make_float2(acc[mi][nj][0] + b0, acc[mi][nj][1] + b1);
                *(float2*)&O[(size_t)r*C + cc] = lo;
            }
            if (r + 8 < N) {
                float2 hi = make_float2(acc[mi][nj][2] + b0, acc[mi][nj][3] + b1);
                *(float2*)&O[(size_t)(r+8)*C + cc] = hi;
            }
        }
    }
}

// ---------------------------------------------------------------------------
extern "C" void kernel_launch(void* const* d_in, const int* in_sizes, int n_in,
                              void* d_out, int out_size) {
    const float* x      = (const float*)d_in[0];   // (128,196,768)
    const float* k_c    = (const float*)d_in[1];   // (768,64)
    const float* v_c    = (const float*)d_in[2];   // (64,196,196)
    const float* proj_w = (const float*)d_in[3];   // (768,768)
    const float* proj_b = (const float*)d_in[4];   // (768,)
    float* out = (float*)d_out;

    attn_kernel<<<B, 256>>>(x, k_c);
    mix_kernel<<<(NM + 255)/256, 256>>>(v_c);
    {
        dim3 grid(C/XT_N, (B*N)/XT_M);             // (6, 196)
        gemm_xw_tf32<<<grid, 256>>>(x, proj_w);
    }
    {
        dim3 grid(C/XT_N, 2, B);                   // (6, 2, 128)
        gemm_out_tf32<<<grid, 256>>>(proj_b, out);
    }
}

// round 4
// speedup vs baseline: 5.2562x; 1.4389x over previous
#include <cuda_runtime.h>
#include <math.h>

// Shapes (fixed by the problem)
#define B   128
#define N   196
#define C   768
#define CTR 64
#define NM  (N*N)          // 38416

// Scratch (device globals: allocation-free rule)
__device__ float g_attn[B*CTR];
__device__ float g_xw[B*N*C];       // x @ proj_w^T   (77 MB)
__device__ float g_v[B*NM];         // attn @ v_c     (19.7 MB)
__device__ float g_qp[B*8*C];       // partial column sums (7 used, pad 8)

__device__ __forceinline__ unsigned f2tf32(float f) {
    unsigned r;
    asm("cvt.rna.tf32.f32 %0, %1;" : "=r"(r) : "f"(f));
    return r;
}

__device__ __forceinline__ void cp16(void* sdst, const void* gsrc, bool pred) {
    unsigned d = (unsigned)__cvta_generic_to_shared(sdst);
    int sz = pred ? 16 : 0;
    asm volatile("cp.async.cg.shared.global [%0], [%1], 16, %2;\n"
                 :: "r"(d), "l"(gsrc), "r"(sz));
}
__device__ __forceinline__ void cp_commit() {
    asm volatile("cp.async.commit_group;\n" ::: "memory");
}
__device__ __forceinline__ void cp_wait0() {
    asm volatile("cp.async.wait_group 0;\n" ::: "memory");
}

// ---------------------------------------------------------------------------
// K1a: partial column sums of x over N (7 chunks of 28 rows per batch)
// ---------------------------------------------------------------------------
__global__ void colsum_kernel(const float* __restrict__ x) {
    const int b = blockIdx.x, j = blockIdx.y;   // j in 0..6
    const int r0 = j * 28;
    const float* xb = x + (size_t)b*N*C;
    for (int c = threadIdx.x; c < C; c += 256) {
        float s = 0.f;
        #pragma unroll
        for (int n = 0; n < 28; n++) s += xb[(size_t)(r0+n)*C + c];
        g_qp[((size_t)b*8 + j)*C + c] = s;
    }
}

// ---------------------------------------------------------------------------
// K1b: finish mean, cosine-sim vs k_c, softmax -> g_attn
// ---------------------------------------------------------------------------
__global__ void attn_kernel(const float* __restrict__ k_c) {
    const int b = blockIdx.x;
    __shared__ float q[C];
    __shared__ float red[256];
    __shared__ float logits[CTR];
    const int tid = threadIdx.x;

    for (int c = tid; c < C; c += 256) {
        float s = 0.f;
        #pragma unroll
        for (int j = 0; j < 7; j++) s += g_qp[((size_t)b*8 + j)*C + c];
        q[c] = s * (1.0f/N);
    }
    __syncthreads();

    float ps = 0.f;
    for (int c = tid; c < C; c += 256) ps += q[c]*q[c];
    red[tid] = ps;
    __syncthreads();
    for (int s = 128; s > 0; s >>= 1) {
        if (tid < s) red[tid] += red[tid+s];
        __syncthreads();
    }
    const float qinv = 1.0f / fmaxf(sqrtf(red[0]), 1e-12f);

    const int warp = tid >> 5, lane = tid & 31;
    for (int c = warp; c < CTR; c += 8) {
        float dot = 0.f, kn = 0.f;
        for (int k = lane; k < C; k += 32) {
            float kv = k_c[k*CTR + c];
            dot += q[k]*kv;
            kn  += kv*kv;
        }
        #pragma unroll
        for (int o = 16; o > 0; o >>= 1) {
            dot += __shfl_down_sync(0xffffffff, dot, o);
            kn  += __shfl_down_sync(0xffffffff, kn, o);
        }
        if (lane == 0) {
            float kinv = 1.0f / fmaxf(sqrtf(kn), 1e-12f);
            logits[c] = dot * qinv * kinv * 0.03608439182435161f; // 768^-0.5
        }
    }
    __syncthreads();

    if (tid == 0) {
        float mx = -1e30f;
        #pragma unroll
        for (int c = 0; c < CTR; c++) mx = fmaxf(mx, logits[c]);
        float sum = 0.f;
        #pragma unroll
        for (int c = 0; c < CTR; c++) { float e = expf(logits[c]-mx); logits[c] = e; sum += e; }
        float inv = 1.0f/sum;
        #pragma unroll
        for (int c = 0; c < CTR; c++) g_attn[b*CTR + c] = logits[c]*inv;
    }
}

// ---------------------------------------------------------------------------
// K2: v[b, nm] = sum_c attn[b,c] * v_c[c, nm]
// ---------------------------------------------------------------------------
__global__ void mix_kernel(const float* __restrict__ v_c) {
    __shared__ float a_s[B*CTR];   // 32 KB
    const int tid = threadIdx.x;
    for (int i = tid; i < B*CTR; i += 256) a_s[i] = g_attn[i];
    __syncthreads();

    const int nm = blockIdx.x*256 + tid;
    if (nm >= NM) return;

    float vr[CTR];
    #pragma unroll
    for (int c = 0; c < CTR; c++) vr[c] = v_c[(size_t)c*NM + nm];

    for (int b = 0; b < B; b++) {
        const float* ap = a_s + b*CTR;
        float acc = 0.f;
        #pragma unroll
        for (int c = 0; c < CTR; c++) acc += ap[c]*vr[c];
        g_v[(size_t)b*NM + nm] = acc;
    }
}

// ---------------------------------------------------------------------------
// K3: xw = x @ proj_w^T via tf32 mma.sync, cp.async double-buffered
// M=25088, N=768, K=768. Block tile 128x128x32, 8 warps, warp tile 64x32.
// As[m][k] and Bs[n][k] both stored row-major (k inner, pad 36) -> cp.async
// needs no transpose; fragments gather scalars.
// ---------------------------------------------------------------------------
__global__ __launch_bounds__(256, 2)
void gemm_xw_tf32(const float* __restrict__ X,
                  const float* __restrict__ W) {
    extern __shared__ float sm[];
    float* As = sm;                 // [2][128][36]
    float* Bs = sm + 2*128*36;      // [2][128][36]

    const int tid  = threadIdx.x;
    const int lane = tid & 31;
    const int w    = tid >> 5;
    const int wm   = (w & 1) * 64;
    const int wn   = (w >> 1) * 32;
    const int bm   = blockIdx.y * 128;
    const int bn   = blockIdx.x * 128;

    const int lr = tid >> 3;          // 0..31
    const int lk = (tid & 7) * 4;     // 0..28

    const int gq = lane >> 2;
    const int tq = lane & 3;

    float acc[4][4][4] = {};

    // prologue: tile 0 -> buffer 0
    #pragma unroll
    for (int i = 0; i < 4; i++) {
        int r = lr + 32*i;
        cp16(&As[(0*128 + r)*36 + lk], &X[(size_t)(bm+r)*C + lk], true);
        cp16(&Bs[(0*128 + r)*36 + lk], &W[(size_t)(bn+r)*C + lk], true);
    }
    cp_commit(); cp_wait0(); __syncthreads();

    const int NITER = C / 32;   // 24
    for (int it = 0; it < NITER; it++) {
        const int cur = it & 1, nxt = cur ^ 1;
        if (it + 1 < NITER) {
            int k0 = (it + 1) * 32;
            #pragma unroll
            for (int i = 0; i < 4; i++) {
                int r = lr + 32*i;
                cp16(&As[(nxt*128 + r)*36 + lk], &X[(size_t)(bm+r)*C + k0 + lk], true);
                cp16(&Bs[(nxt*128 + r)*36 + lk], &W[(size_t)(bn+r)*C + k0 + lk], true);
            }
            cp_commit();
        }

        const float* Ac = &As[cur*128*36];
        const float* Bc = &Bs[cur*128*36];
        #pragma unroll
        for (int ks = 0; ks < 4; ks++) {
            const int kb = ks * 8;
            unsigned af[4][4], bf[4][2];
            #pragma unroll
            for (int mi = 0; mi < 4; mi++) {
                int r = wm + mi*16 + gq;
                af[mi][0] = f2tf32(Ac[(size_t)r*36     + kb + tq    ]);
                af[mi][1] = f2tf32(Ac[(size_t)(r+8)*36 + kb + tq    ]);
                af[mi][2] = f2tf32(Ac[(size_t)r*36     + kb + tq + 4]);
                af[mi][3] = f2tf32(Ac[(size_t)(r+8)*36 + kb + tq + 4]);
            }
            #pragma unroll
            for (int nj = 0; nj < 4; nj++) {
                int cn = wn + nj*8 + gq;
                bf[nj][0] = f2tf32(Bc[(size_t)cn*36 + kb + tq    ]);
                bf[nj][1] = f2tf32(Bc[(size_t)cn*36 + kb + tq + 4]);
            }
            #pragma unroll
            for (int mi = 0; mi < 4; mi++)
                #pragma unroll
                for (int nj = 0; nj < 4; nj++) {
                    asm volatile(
                        "mma.sync.aligned.m16n8k8.row.col.f32.tf32.tf32.f32 "
                        "{%0,%1,%2,%3}, {%4,%5,%6,%7}, {%8,%9}, {%0,%1,%2,%3};"
                        : "+f"(acc[mi][nj][0]), "+f"(acc[mi][nj][1]),
                          "+f"(acc[mi][nj][2]), "+f"(acc[mi][nj][3])
                        : "r"(af[mi][0]), "r"(af[mi][1]), "r"(af[mi][2]), "r"(af[mi][3]),
                          "r"(bf[nj][0]), "r"(bf[nj][1]));
                }
        }
        if (it + 1 < NITER) cp_wait0();
        __syncthreads();
    }

    #pragma unroll
    for (int mi = 0; mi < 4; mi++) {
        #pragma unroll
        for (int nj = 0; nj < 4; nj++) {
            int r  = bm + wm + mi*16 + gq;
            int cc = bn + wn + nj*8 + tq*2;
            float2 lo = make_float2(acc[mi][nj][0], acc[mi][nj][1]);
            float2 hi = make_float2(acc[mi][nj][2], acc[mi][nj][3]);
            *(float2*)&g_xw[(size_t)r*C + cc]     = lo;
            *(float2*)&g_xw[(size_t)(r+8)*C + cc] = hi;
        }
    }
}

// ---------------------------------------------------------------------------
// K4: out[b] = v[b] @ xw[b] + bias via tf32 mma.sync, cp.async double-buffered
// Per batch: M=196, N=768, K=196. As[m][k] (pad 36), Bs[k][n] (pad 132).
// ---------------------------------------------------------------------------
__global__ __launch_bounds__(256, 2)
void gemm_out_tf32(const float* __restrict__ bias,
                   float* __restrict__ OUT) {
    extern __shared__ float sm[];
    float* As = sm;                 // [2][128][36]
    float* Bs = sm + 2*128*36;      // [2][32][132]

    const int b  = blockIdx.z;
    const float* A  = g_v  + (size_t)b*NM;     // (196,196)
    const float* Bm = g_xw + (size_t)b*N*C;    // (196,768)
    float* O = OUT + (size_t)b*N*C;

    const int tid  = threadIdx.x;
    const int lane = tid & 31;
    const int w    = tid >> 5;
    const int wm   = (w & 1) * 64;
    const int wn   = (w >> 1) * 32;
    const int bm   = blockIdx.y * 128;         // 0 or 128
    const int bn   = blockIdx.x * 128;         // 0..640

    const int lr = tid >> 3;                   // A: row 0..31 (+32i)
    const int lk = (tid & 7) * 4;              // A: k
    const int bk = tid >> 3;                   // B: k-row 0..31
    const int bn4 = (tid & 7) * 4;             // B: n (+32i)

    const int gq = lane >> 2;
    const int tq = lane & 3;

    float acc[4][4][4] = {};

    // prologue: tile 0 -> buffer 0
    #pragma unroll
    for (int i = 0; i < 4; i++) {
        int m = lr + 32*i;
        cp16(&As[(0*128 + m)*36 + lk], &A[(size_t)(bm+m)*N + lk],
             (bm + m < N) && (lk < N));
        int n = bn4 + 32*i;
        cp16(&Bs[(size_t)(0*32 + bk)*132 + n], &Bm[(size_t)bk*C + bn + n],
             bk < N);
    }
    cp_commit(); cp_wait0(); __syncthreads();

    const int NITER = (N + 31) / 32;   // 7
    for (int it = 0; it < NITER; it++) {
        const int cur = it & 1, nxt = cur ^ 1;
        if (it + 1 < NITER) {
            int k0 = (it + 1) * 32;
            #pragma unroll
            for (int i = 0; i < 4; i++) {
                int m = lr + 32*i;
                cp16(&As[(nxt*128 + m)*36 + lk], &A[(size_t)(bm+m)*N + k0 + lk],
                     (bm + m < N) && (k0 + lk < N));
                int n = bn4 + 32*i;
                cp16(&Bs[(size_t)(nxt*32 + bk)*132 + n], &Bm[(size_t)(k0+bk)*C + bn + n],
                     (k0 + bk) < N);
            }
            cp_commit();
        }

        const float* Ac = &As[cur*128*36];
        const float* Bc = &Bs[(size_t)cur*32*132];
        #pragma unroll
        for (int ks = 0; ks < 4; ks++) {
            const int kb = ks * 8;
            unsigned af[4][4], bf[4][2];
            #pragma unroll
            for (int mi = 0; mi < 4; mi++) {
                int r = wm + mi*16 + gq;
                af[mi][0] = f2tf32(Ac[(size_t)r*36     + kb + tq    ]);
                af[mi][1] = f2tf32(Ac[(size_t)(r+8)*36 + kb + tq    ]);
                af[mi][2] = f2tf32(Ac[(size_t)r*36     + kb + tq + 4]);
                af[mi][3] = f2tf32(Ac[(size_t)(r+8)*36 + kb + tq + 4]);
            }
            #pragma unroll
            for (int nj = 0; nj < 4; nj++) {
                int cn = wn + nj*8 + gq;
                bf[nj][0] = f2tf32(Bc[(size_t)(kb+tq  )*132 + cn]);
                bf[nj][1] = f2tf32(Bc[(size_t)(kb+tq+4)*132 + cn]);
            }
            #pragma unroll
            for (int mi = 0; mi < 4; mi++)
                #pragma unroll
                for (int nj = 0; nj < 4; nj++) {
                    asm volatile(
                        "mma.sync.aligned.m16n8k8.row.col.f32.tf32.tf32.f32 "
                        "{%0,%1,%2,%3}, {%4,%5,%6,%7}, {%8,%9}, {%0,%1,%2,%3};"
                        : "+f"(acc[mi][nj][0]), "+f"(acc[mi][nj][1]),
                          "+f"(acc[mi][nj][2]), "+f"(acc[mi][nj][3])
                        : "r"(af[mi][0]), "r"(af[mi][1]), "r"(af[mi][2]), "r"(af[mi][3]),
                          "r"(bf[nj][0]), "r"(bf[nj][1]));
                }
        }
        if (it + 1 < NITER) cp_wait0();
        __syncthreads();
    }

    // epilogue with bias; guard rows < 196
    #pragma unroll
    for (int mi = 0; mi < 4; mi++) {
        #pragma unroll
        for (int nj = 0; nj < 4; nj++) {
            int r  = bm + wm + mi*16 + gq;
            int cc = bn + wn + nj*8 + tq*2;
            float b0 = bias[cc], b1 = bias[cc+1];
            if (r < N) {
                float2 lo = make_float2(acc[mi][nj][0] + b0, acc[mi][nj][1] + b1);
                *(float2*)&O[(size_t)r*C + cc] = lo;
            }
            if (r + 8 < N) {
                float2 hi = make_float2(acc[mi][nj][2] + b0, acc[mi][nj][3] + b1);
                *(float2*)&O[(size_t)(r+8)*C + cc] = hi;
            }
        }
    }
}

// ---------------------------------------------------------------------------
extern "C" void kernel_launch(void* const* d_in, const int* in_sizes, int n_in,
                              void* d_out, int out_size) {
    const float* x      = (const float*)d_in[0];   // (128,196,768)
    const float* k_c    = (const float*)d_in[1];   // (768,64)
    const float* v_c    = (const float*)d_in[2];   // (64,196,196)
    const float* proj_w = (const float*)d_in[3];   // (768,768)
    const float* proj_b = (const float*)d_in[4];   // (768,)
    float* out = (float*)d_out;

    const int SMEM_XW  = 2*128*36*2 * (int)sizeof(float);            // 73728
    const int SMEM_OUT = (2*128*36 + 2*32*132) * (int)sizeof(float); // 70656
    cudaFuncSetAttribute(gemm_xw_tf32,  cudaFuncAttributeMaxDynamicSharedMemorySize, SMEM_XW);
    cudaFuncSetAttribute(gemm_out_tf32, cudaFuncAttributeMaxDynamicSharedMemorySize, SMEM_OUT);

    {
        dim3 grid(B, 7);
        colsum_kernel<<<grid, 256>>>(x);
    }
    attn_kernel<<<B, 256>>>(k_c);
    mix_kernel<<<(NM + 255)/256, 256>>>(v_c);
    {
        dim3 grid(C/128, (B*N)/128);               // (6, 196)
        gemm_xw_tf32<<<grid, 256, SMEM_XW>>>(x, proj_w);
    }
    {
        dim3 grid(C/128, 2, B);                    // (6, 2, 128)
        gemm_out_tf32<<<grid, 256, SMEM_OUT>>>(proj_b, out);
    }
}

// round 6
// speedup vs baseline: 5.5016x; 1.0467x over previous
#include <cuda_runtime.h>
#include <math.h>

// Shapes (fixed by the problem)
#define B   128
#define N   196
#define C   768
#define CTR 64
#define NM  (N*N)          // 38416

// Scratch (device globals: allocation-free rule)
__device__ float g_attn[B*CTR];
__device__ float g_xw[B*N*C];       // x @ proj_w^T, tf32-rounded at write (77 MB)
__device__ float g_v[B*NM];         // attn @ v_c, tf32-rounded at write (19.7 MB)
__device__ float g_qp[B*8*C];       // partial column sums (7 used, pad 8)
__device__ unsigned g_xt[(size_t)B*N*C];  // tf32 bits of x (77 MB)
__device__ unsigned g_wt[C*C];            // tf32 bits of proj_w

__device__ __forceinline__ unsigned f2tf32(float f) {
    unsigned r;
    asm("cvt.rna.tf32.f32 %0, %1;" : "=r"(r) : "f"(f));
    return r;
}

__device__ __forceinline__ void cp16(void* sdst, const void* gsrc, bool pred) {
    unsigned d = (unsigned)__cvta_generic_to_shared(sdst);
    int sz = pred ? 16 : 0;
    asm volatile("cp.async.cg.shared.global [%0], [%1], 16, %2;\n"
                 :: "r"(d), "l"(gsrc), "r"(sz));
}
__device__ __forceinline__ void cp_commit() {
    asm volatile("cp.async.commit_group;\n" ::: "memory");
}
__device__ __forceinline__ void cp_wait0() {
    asm volatile("cp.async.wait_group 0;\n" ::: "memory");
}

// ---------------------------------------------------------------------------
// K0: proj_w -> tf32 bits
// ---------------------------------------------------------------------------
__global__ void split_w_kernel(const float* __restrict__ w) {
    int i = blockIdx.x * 256 + threadIdx.x;
    if (i < C*C) g_wt[i] = f2tf32(w[i]);
}

// ---------------------------------------------------------------------------
// K1a: x -> tf32 bits AND partial column sums (fused single read)
// ---------------------------------------------------------------------------
__global__ void split_x_kernel(const float* __restrict__ x) {
    const int b = blockIdx.x, j = blockIdx.y;   // j in 0..6
    const int r0 = j * 28;
    const float* xb = x + (size_t)b*N*C;
    for (int c = threadIdx.x; c < C; c += 256) {
        float s = 0.f;
        #pragma unroll 4
        for (int n = 0; n < 28; n++) {
            size_t idx = (size_t)(r0+n)*C + c;
            float v = xb[idx];
            g_xt[(size_t)b*N*C + idx] = f2tf32(v);
            s += v;
        }
        g_qp[((size_t)b*8 + j)*C + c] = s;
    }
}

// ---------------------------------------------------------------------------
// K1b: finish mean, cosine-sim vs k_c, softmax -> g_attn
// ---------------------------------------------------------------------------
__global__ void attn_kernel(const float* __restrict__ k_c) {
    const int b = blockIdx.x;
    __shared__ float q[C];
    __shared__ float red[256];
    __shared__ float logits[CTR];
    const int tid = threadIdx.x;

    for (int c = tid; c < C; c += 256) {
        float s = 0.f;
        #pragma unroll
        for (int j = 0; j < 7; j++) s += g_qp[((size_t)b*8 + j)*C + c];
        q[c] = s * (1.0f/N);
    }
    __syncthreads();

    float ps = 0.f;
    for (int c = tid; c < C; c += 256) ps += q[c]*q[c];
    red[tid] = ps;
    __syncthreads();
    for (int s = 128; s > 0; s >>= 1) {
        if (tid < s) red[tid] += red[tid+s];
        __syncthreads();
    }
    const float qinv = 1.0f / fmaxf(sqrtf(red[0]), 1e-12f);

    const int warp = tid >> 5, lane = tid & 31;
    for (int c = warp; c < CTR; c += 8) {
        float dot = 0.f, kn = 0.f;
        for (int k = lane; k < C; k += 32) {
            float kv = k_c[k*CTR + c];
            dot += q[k]*kv;
            kn  += kv*kv;
        }
        #pragma unroll
        for (int o = 16; o > 0; o >>= 1) {
            dot += __shfl_down_sync(0xffffffff, dot, o);
            kn  += __shfl_down_sync(0xffffffff, kn, o);
        }
        if (lane == 0) {
            float kinv = 1.0f / fmaxf(sqrtf(kn), 1e-12f);
            logits[c] = dot * qinv * kinv * 0.03608439182435161f; // 768^-0.5
        }
    }
    __syncthreads();

    if (tid == 0) {
        float mx = -1e30f;
        #pragma unroll
        for (int c = 0; c < CTR; c++) mx = fmaxf(mx, logits[c]);
        float sum = 0.f;
        #pragma unroll
        for (int c = 0; c < CTR; c++) { float e = expf(logits[c]-mx); logits[c] = e; sum += e; }
        float inv = 1.0f/sum;
        #pragma unroll
        for (int c = 0; c < CTR; c++) g_attn[b*CTR + c] = logits[c]*inv;
    }
}

// ---------------------------------------------------------------------------
// K2: v[b, nm] = sum_c attn[b,c] * v_c[c, nm]  (tf32-rounded at write)
// ---------------------------------------------------------------------------
__global__ void mix_kernel(const float* __restrict__ v_c) {
    __shared__ float a_s[B*CTR];   // 32 KB
    const int tid = threadIdx.x;
    for (int i = tid; i < B*CTR; i += 256) a_s[i] = g_attn[i];
    __syncthreads();

    const int nm = blockIdx.x*256 + tid;
    if (nm >= NM) return;

    float vr[CTR];
    #pragma unroll
    for (int c = 0; c < CTR; c++) vr[c] = v_c[(size_t)c*NM + nm];

    for (int b = 0; b < B; b++) {
        const float* ap = a_s + b*CTR;
        float acc = 0.f;
        #pragma unroll
        for (int c = 0; c < CTR; c++) acc += ap[c]*vr[c];
        g_v[(size_t)b*NM + nm] = __uint_as_float(f2tf32(acc));
    }
}

// ---------------------------------------------------------------------------
// K3: xw = x @ proj_w^T via tf32 mma.sync, cp.async double-buffered,
// zero in-loop conversions (operands pre-converted to tf32 bits).
// M=25088, N=768, K=768. Block tile 128x128x32, 8 warps, warp tile 64x32.
// ---------------------------------------------------------------------------
__global__ __launch_bounds__(256, 2)
void gemm_xw_tf32() {
    extern __shared__ unsigned smu[];
    unsigned* As = smu;                 // [2][128][36]
    unsigned* Bs = smu + 2*128*36;      // [2][128][36]

    const int tid  = threadIdx.x;
    const int lane = tid & 31;
    const int w    = tid >> 5;
    const int wm   = (w & 1) * 64;
    const int wn   = (w >> 1) * 32;
    const int bm   = blockIdx.y * 128;
    const int bn   = blockIdx.x * 128;

    const int lr = tid >> 3;          // 0..31
    const int lk = (tid & 7) * 4;     // 0..28

    const int gq = lane >> 2;
    const int tq = lane & 3;

    float acc[4][4][4] = {};

    // prologue: tile 0 -> buffer 0
    #pragma unroll
    for (int i = 0; i < 4; i++) {
        int r = lr + 32*i;
        cp16(&As[(0*128 + r)*36 + lk], &g_xt[(size_t)(bm+r)*C + lk], true);
        cp16(&Bs[(0*128 + r)*36 + lk], &g_wt[(size_t)(bn+r)*C + lk], true);
    }
    cp_commit(); cp_wait0(); __syncthreads();

    const int NITER = C / 32;   // 24
    for (int it = 0; it < NITER; it++) {
        const int cur = it & 1, nxt = cur ^ 1;
        if (it + 1 < NITER) {
            int k0 = (it + 1) * 32;
            #pragma unroll
            for (int i = 0; i < 4; i++) {
                int r = lr + 32*i;
                cp16(&As[(nxt*128 + r)*36 + lk], &g_xt[(size_t)(bm+r)*C + k0 + lk], true);
                cp16(&Bs[(nxt*128 + r)*36 + lk], &g_wt[(size_t)(bn+r)*C + k0 + lk], true);
            }
            cp_commit();
        }

        const unsigned* Ac = &As[cur*128*36];
        const unsigned* Bc = &Bs[cur*128*36];
        #pragma unroll
        for (int ks = 0; ks < 4; ks++) {
            const int kb = ks * 8;
            unsigned af[4][4], bf[4][2];
            #pragma unroll
            for (int mi = 0; mi < 4; mi++) {
                int r = wm + mi*16 + gq;
                af[mi][0] = Ac[(size_t)r*36     + kb + tq    ];
                af[mi][1] = Ac[(size_t)(r+8)*36 + kb + tq    ];
                af[mi][2] = Ac[(size_t)r*36     + kb + tq + 4];
                af[mi][3] = Ac[(size_t)(r+8)*36 + kb + tq + 4];
            }
            #pragma unroll
            for (int nj = 0; nj < 4; nj++) {
                int cn = wn + nj*8 + gq;
                bf[nj][0] = Bc[(size_t)cn*36 + kb + tq    ];
                bf[nj][1] = Bc[(size_t)cn*36 + kb + tq + 4];
            }
            #pragma unroll
            for (int mi = 0; mi < 4; mi++)
                #pragma unroll
                for (int nj = 0; nj < 4; nj++) {
                    asm volatile(
                        "mma.sync.aligned.m16n8k8.row.col.f32.tf32.tf32.f32 "
                        "{%0,%1,%2,%3}, {%4,%5,%6,%7}, {%8,%9}, {%0,%1,%2,%3};"
                        : "+f"(acc[mi][nj][0]), "+f"(acc[mi][nj][1]),
                          "+f"(acc[mi][nj][2]), "+f"(acc[mi][nj][3])
                        : "r"(af[mi][0]), "r"(af[mi][1]), "r"(af[mi][2]), "r"(af[mi][3]),
                          "r"(bf[nj][0]), "r"(bf[nj][1]));
                }
        }
        if (it + 1 < NITER) cp_wait0();
        __syncthreads();
    }

    // epilogue: round to tf32 at write so gemm_out needs no cvt
    #pragma unroll
    for (int mi = 0; mi < 4; mi++) {
        #pragma unroll
        for (int nj = 0; nj < 4; nj++) {
            int r  = bm + wm + mi*16 + gq;
            int cc = bn + wn + nj*8 + tq*2;
            float2 lo = make_float2(__uint_as_float(f2tf32(acc[mi][nj][0])),
                                    __uint_as_float(f2tf32(acc[mi][nj][1])));
            float2 hi = make_float2(__uint_as_float(f2tf32(acc[mi][nj][2])),
                                    __uint_as_float(f2tf32(acc[mi][nj][3])));
            *(float2*)&g_xw[(size_t)r*C + cc]     = lo;
            *(float2*)&g_xw[(size_t)(r+8)*C + cc] = hi;
        }
    }
}

// ---------------------------------------------------------------------------
// K4: out[b] = v[b] @ xw[b] + bias via tf32 mma.sync, cp.async double-buffered,
// zero in-loop conversions (g_v and g_xw already tf32-rounded).
// Per batch: M=196, N=768, K=196. As[m][k] (pad 36), Bs[k][n] (pad 132).
// ---------------------------------------------------------------------------
__global__ __launch_bounds__(256, 2)
void gemm_out_tf32(const float* __restrict__ bias,
                   float* __restrict__ OUT) {
    extern __shared__ unsigned smu[];
    unsigned* As = smu;                 // [2][128][36]
    unsigned* Bs = smu + 2*128*36;      // [2][32][132]

    const int b  = blockIdx.z;
    const float* A  = g_v  + (size_t)b*NM;     // (196,196)
    const float* Bm = g_xw + (size_t)b*N*C;    // (196,768)
    float* O = OUT + (size_t)b*N*C;

    const int tid  = threadIdx.x;
    const int lane = tid & 31;
    const int w    = tid >> 5;
    const int wm   = (w & 1) * 64;
    const int wn   = (w >> 1) * 32;
    const int bm   = blockIdx.y * 128;         // 0 or 128
    const int bn   = blockIdx.x * 128;         // 0..640

    const int lr = tid >> 3;                   // A: row 0..31 (+32i)
    const int lk = (tid & 7) * 4;              // A: k
    const int bk = tid >> 3;                   // B: k-row 0..31
    const int bn4 = (tid & 7) * 4;             // B: n (+32i)

    const int gq = lane >> 2;
    const int tq = lane & 3;

    float acc[4][4][4] = {};

    #pragma unroll
    for (int i = 0; i < 4; i++) {
        int m = lr + 32*i;
        cp16(&As[(0*128 + m)*36 + lk], &A[(size_t)(bm+m)*N + lk],
             (bm + m < N) && (lk < N));
        int n = bn4 + 32*i;
        cp16(&Bs[(size_t)(0*32 + bk)*132 + n], &Bm[(size_t)bk*C + bn + n],
             bk < N);
    }
    cp_commit(); cp_wait0(); __syncthreads();

    const int NITER = (N + 31) / 32;   // 7
    for (int it = 0; it < NITER; it++) {
        const int cur = it & 1, nxt = cur ^ 1;
        if (it + 1 < NITER) {
            int k0 = (it + 1) * 32;
            #pragma unroll
            for (int i = 0; i < 4; i++) {
                int m = lr + 32*i;
                cp16(&As[(nxt*128 + m)*36 + lk], &A[(size_t)(bm+m)*N + k0 + lk],
                     (bm + m < N) && (k0 + lk < N));
                int n = bn4 + 32*i;
                cp16(&Bs[(size_t)(nxt*32 + bk)*132 + n], &Bm[(size_t)(k0+bk)*C + bn + n],
                     (k0 + bk) < N);
            }
            cp_commit();
        }

        const unsigned* Ac = &As[cur*128*36];
        const unsigned* Bc = &Bs[(size_t)cur*32*132];
        #pragma unroll
        for (int ks = 0; ks < 4; ks++) {
            const int kb = ks * 8;
            unsigned af[4][4], bf[4][2];
            #pragma unroll
            for (int mi = 0; mi < 4; mi++) {
                int r = wm + mi*16 + gq;
                af[mi][0] = Ac[(size_t)r*36     + kb + tq    ];
                af[mi][1] = Ac[(size_t)(r+8)*36 + kb + tq    ];
                af[mi][2] = Ac[(size_t)r*36     + kb + tq + 4];
                af[mi][3] = Ac[(size_t)(r+8)*36 + kb + tq + 4];
            }
            #pragma unroll
            for (int nj = 0; nj < 4; nj++) {
                int cn = wn + nj*8 + gq;
                bf[nj][0] = Bc[(size_t)(kb+tq  )*132 + cn];
                bf[nj][1] = Bc[(size_t)(kb+tq+4)*132 + cn];
            }
            #pragma unroll
            for (int mi = 0; mi < 4; mi++)
                #pragma unroll
                for (int nj = 0; nj < 4; nj++) {
                    asm volatile(
                        "mma.sync.aligned.m16n8k8.row.col.f32.tf32.tf32.f32 "
                        "{%0,%1,%2,%3}, {%4,%5,%6,%7}, {%8,%9}, {%0,%1,%2,%3};"
                        : "+f"(acc[mi][nj][0]), "+f"(acc[mi][nj][1]),
                          "+f"(acc[mi][nj][2]), "+f"(acc[mi][nj][3])
                        : "r"(af[mi][0]), "r"(af[mi][1]), "r"(af[mi][2]), "r"(af[mi][3]),
                          "r"(bf[nj][0]), "r"(bf[nj][1]));
                }
        }
        if (it + 1 < NITER) cp_wait0();
        __syncthreads();
    }

    #pragma unroll
    for (int mi = 0; mi < 4; mi++) {
        #pragma unroll
        for (int nj = 0; nj < 4; nj++) {
            int r  = bm + wm + mi*16 + gq;
            int cc = bn + wn + nj*8 + tq*2;
            float b0 = bias[cc], b1 = bias[cc+1];
            if (r < N) {
                float2 lo = make_float2(acc[mi][nj][0] + b0, acc[mi][nj][1] + b1);
                *(float2*)&O[(size_t)r*C + cc] = lo;
            }
            if (r + 8 < N) {
                float2 hi = make_float2(acc[mi][nj][2] + b0, acc[mi][nj][3] + b1);
                *(float2*)&O[(size_t)(r+8)*C + cc] = hi;
            }
        }
    }
}

// ---------------------------------------------------------------------------
extern "C" void kernel_launch(void* const* d_in, const int* in_sizes, int n_in,
                              void* d_out, int out_size) {
    const float* x      = (const float*)d_in[0];   // (128,196,768)
    const float* k_c    = (const float*)d_in[1];   // (768,64)
    const float* v_c    = (const float*)d_in[2];   // (64,196,196)
    const float* proj_w = (const float*)d_in[3];   // (768,768)
    const float* proj_b = (const float*)d_in[4];   // (768,)
    float* out = (float*)d_out;

    const int SMEM_XW  = 2*128*36*2 * (int)sizeof(float);            // 73728
    const int SMEM_OUT = (2*128*36 + 2*32*132) * (int)sizeof(float); // 70656
    cudaFuncSetAttribute(gemm_xw_tf32,  cudaFuncAttributeMaxDynamicSharedMemorySize, SMEM_XW);
    cudaFuncSetAttribute(gemm_out_tf32, cudaFuncAttributeMaxDynamicSharedMemorySize, SMEM_OUT);

    split_w_kernel<<<(C*C + 255)/256, 256>>>(proj_w);
    {
        dim3 grid(B, 7);
        split_x_kernel<<<grid, 256>>>(x);
    }
    attn_kernel<<<B, 256>>>(k_c);
    mix_kernel<<<(NM + 255)/256, 256>>>(v_c);
    {
        dim3 grid(C/128, (B*N)/128);               // (6, 196)
        gemm_xw_tf32<<<grid, 256, SMEM_XW>>>();
    }
    {
        dim3 grid(C/128, 2, B);                    // (6, 2, 128)
        gemm_out_tf32<<<grid, 256, SMEM_OUT>>>(proj_b, out);
    }
}

// round 7
// speedup vs baseline: 6.8391x; 1.2431x over previous
#include <cuda_runtime.h>
#include <cuda_fp16.h>
#include <math.h>

// Shapes (fixed by the problem)
#define B   128
#define N   196
#define C   768
#define CTR 64
#define NM  (N*N)          // 38416
#define VP  200            // padded row length (halves) for v / xwT, 16B-aligned rows
#define KH  64             // k-tile (halves) per pipeline stage
#define RS  72             // smem row stride (halves): 64 data + 8 pad (conflict-free frags)
#define SST 136            // epilogue staging stride (halves)

// Scratch (device globals: allocation-free rule)
__device__ float g_attn[B*CTR];
__device__ float g_qp[B*8*C];                    // partial column sums (7 used, pad 8)
__device__ __half g_xh[(size_t)B*N*C];           // fp16 x                (38.6 MB)
__device__ __half g_wh[(size_t)C*C];             // fp16 proj_w [n][k]
__device__ __half g_v16[(size_t)B*N*VP];         // fp16 v, rows padded   (10 MB)
__device__ __half g_xwT[(size_t)B*C*VP];         // fp16 xw TRANSPOSED [b][c][t] (39.3 MB)

__device__ __forceinline__ void cp16(void* sdst, const void* gsrc, bool pred) {
    unsigned d = (unsigned)__cvta_generic_to_shared(sdst);
    int sz = pred ? 16 : 0;
    asm volatile("cp.async.cg.shared.global [%0], [%1], 16, %2;\n"
                 :: "r"(d), "l"(gsrc), "r"(sz));
}
__device__ __forceinline__ void cp_commit() {
    asm volatile("cp.async.commit_group;\n" ::: "memory");
}
__device__ __forceinline__ void cp_wait0() {
    asm volatile("cp.async.wait_group 0;\n" ::: "memory");
}

#define MMA_F16(acc, af, bf)                                                  \
    asm volatile(                                                             \
        "mma.sync.aligned.m16n8k16.row.col.f32.f16.f16.f32 "                  \
        "{%0,%1,%2,%3}, {%4,%5,%6,%7}, {%8,%9}, {%0,%1,%2,%3};"               \
        : "+f"((acc)[0]), "+f"((acc)[1]), "+f"((acc)[2]), "+f"((acc)[3])      \
        : "r"((af)[0]), "r"((af)[1]), "r"((af)[2]), "r"((af)[3]),             \
          "r"((bf)[0]), "r"((bf)[1]))

// ---------------------------------------------------------------------------
// K-1: zero the 4-half row pads of g_v16 and g_xwT (keeps MMA k-overrun = 0*0)
// ---------------------------------------------------------------------------
__global__ void pad_kernel() {
    int row = blockIdx.x * 256 + threadIdx.x;
    const int NV = B * N;           // 25088 rows of g_v16
    const int NX = B * C;           // 98304 rows of g_xwT
    if (row < NV) {
        *(unsigned long long*)&g_v16[(size_t)row*VP + N] = 0ull;
    } else if (row < NV + NX) {
        int r2 = row - NV;
        *(unsigned long long*)&g_xwT[(size_t)r2*VP + N] = 0ull;
    }
}

// ---------------------------------------------------------------------------
// K0: proj_w -> fp16
// ---------------------------------------------------------------------------
__global__ void split_w_kernel(const float* __restrict__ w) {
    int i = blockIdx.x * 256 + threadIdx.x;
    if (i < C*C) g_wh[i] = __float2half(w[i]);
}

// ---------------------------------------------------------------------------
// K1a: x -> fp16 AND partial column sums (fused single read)
// ---------------------------------------------------------------------------
__global__ void split_x_kernel(const float* __restrict__ x) {
    const int b = blockIdx.x, j = blockIdx.y;   // j in 0..6
    const int r0 = j * 28;
    const float* xb = x + (size_t)b*N*C;
    for (int c = threadIdx.x; c < C; c += 256) {
        float s = 0.f;
        #pragma unroll 4
        for (int n = 0; n < 28; n++) {
            size_t idx = (size_t)(r0+n)*C + c;
            float v = xb[idx];
            g_xh[(size_t)b*N*C + idx] = __float2half(v);
            s += v;
        }
        g_qp[((size_t)b*8 + j)*C + c] = s;
    }
}

// ---------------------------------------------------------------------------
// K1b: finish mean, cosine-sim vs k_c, softmax -> g_attn
// ---------------------------------------------------------------------------
__global__ void attn_kernel(const float* __restrict__ k_c) {
    const int b = blockIdx.x;
    __shared__ float q[C];
    __shared__ float red[256];
    __shared__ float logits[CTR];
    const int tid = threadIdx.x;

    for (int c = tid; c < C; c += 256) {
        float s = 0.f;
        #pragma unroll
        for (int j = 0; j < 7; j++) s += g_qp[((size_t)b*8 + j)*C + c];
        q[c] = s * (1.0f/N);
    }
    __syncthreads();

    float ps = 0.f;
    for (int c = tid; c < C; c += 256) ps += q[c]*q[c];
    red[tid] = ps;
    __syncthreads();
    for (int s = 128; s > 0; s >>= 1) {
        if (tid < s) red[tid] += red[tid+s];
        __syncthreads();
    }
    const float qinv = 1.0f / fmaxf(sqrtf(red[0]), 1e-12f);

    const int warp = tid >> 5, lane = tid & 31;
    for (int c = warp; c < CTR; c += 8) {
        float dot = 0.f, kn = 0.f;
        for (int k = lane; k < C; k += 32) {
            float kv = k_c[k*CTR + c];
            dot += q[k]*kv;
            kn  += kv*kv;
        }
        #pragma unroll
        for (int o = 16; o > 0; o >>= 1) {
            dot += __shfl_down_sync(0xffffffff, dot, o);
            kn  += __shfl_down_sync(0xffffffff, kn, o);
        }
        if (lane == 0) {
            float kinv = 1.0f / fmaxf(sqrtf(kn), 1e-12f);
            logits[c] = dot * qinv * kinv * 0.03608439182435161f; // 768^-0.5
        }
    }
    __syncthreads();

    if (tid == 0) {
        float mx = -1e30f;
        #pragma unroll
        for (int c = 0; c < CTR; c++) mx = fmaxf(mx, logits[c]);
        float sum = 0.f;
        #pragma unroll
        for (int c = 0; c < CTR; c++) { float e = expf(logits[c]-mx); logits[c] = e; sum += e; }
        float inv = 1.0f/sum;
        #pragma unroll
        for (int c = 0; c < CTR; c++) g_attn[b*CTR + c] = logits[c]*inv;
    }
}

// ---------------------------------------------------------------------------
// K2: v[b][n][m] = sum_c attn[b,c] * v_c[c][n][m]  (fp16, padded rows)
// 4-way batch split for occupancy (grid.y = 4, 32 batches each)
// ---------------------------------------------------------------------------
__global__ void mix_kernel(const float* __restrict__ v_c) {
    __shared__ float a_s[32*CTR];   // 8 KB
    const int tid = threadIdx.x;
    const int g   = blockIdx.y;
    for (int i = tid; i < 32*CTR; i += 256) a_s[i] = g_attn[g*32*CTR + i];
    __syncthreads();

    const int nm = blockIdx.x*256 + tid;
    if (nm >= NM) return;
    const int n = nm / N, m = nm - n * N;

    float vr[CTR];
    #pragma unroll
    for (int c = 0; c < CTR; c++) vr[c] = v_c[(size_t)c*NM + nm];

    for (int b = 0; b < 32; b++) {
        const float* ap = a_s + b*CTR;
        float acc = 0.f;
        #pragma unroll
        for (int c = 0; c < CTR; c++) acc += ap[c]*vr[c];
        g_v16[((size_t)(g*32 + b)*N + n)*VP + m] = __float2half(acc);
    }
}

// ---------------------------------------------------------------------------
// K3: xw = x @ proj_w^T via fp16 mma.sync m16n8k16, cp.async double-buffered.
// M=25088, N=768, K=768. Block 128x128, K-tile 64, 8 warps, warp tile 64x32.
// Output written TRANSPOSED to g_xwT[b][c][t] via smem-staged epilogue.
// ---------------------------------------------------------------------------
__global__ __launch_bounds__(256, 2)
void gemm_xw_f16() {
    extern __shared__ __half smh[];
    __half* As = smh;                  // [2][128][RS]
    __half* Bs = smh + 2*128*RS;       // [2][128][RS]

    const int tid  = threadIdx.x;
    const int lane = tid & 31;
    const int w    = tid >> 5;
    const int wm   = (w & 1) * 64;
    const int wn   = (w >> 1) * 32;
    const int bm   = blockIdx.y * 128;
    const int bn   = blockIdx.x * 128;

    const int lrow = tid >> 1;            // 0..127
    const int lko  = (tid & 1) * 32;      // half offset base; 4 chunks of 8 halves

    const int gq = lane >> 2;
    const int tq = lane & 3;

    float acc[4][4][4] = {};

    // prologue: tile 0 -> buffer 0
    #pragma unroll
    for (int cch = 0; cch < 4; cch++) {
        int ko = lko + cch*8;
        cp16(&As[(size_t)lrow*RS + ko], &g_xh[(size_t)(bm+lrow)*C + ko], true);
        cp16(&Bs[(size_t)lrow*RS + ko], &g_wh[(size_t)(bn+lrow)*C + ko], true);
    }
    cp_commit(); cp_wait0(); __syncthreads();

    const int NITER = C / KH;   // 12
    for (int it = 0; it < NITER; it++) {
        const int cur = it & 1, nxt = cur ^ 1;
        if (it + 1 < NITER) {
            int k0 = (it + 1) * KH;
            #pragma unroll
            for (int cch = 0; cch < 4; cch++) {
                int ko = lko + cch*8;
                cp16(&As[((size_t)nxt*128 + lrow)*RS + ko],
                     &g_xh[(size_t)(bm+lrow)*C + k0 + ko], true);
                cp16(&Bs[((size_t)nxt*128 + lrow)*RS + ko],
                     &g_wh[(size_t)(bn+lrow)*C + k0 + ko], true);
            }
            cp_commit();
        }

        const __half* Ac = &As[(size_t)cur*128*RS];
        const __half* Bc = &Bs[(size_t)cur*128*RS];
        #pragma unroll
        for (int ks = 0; ks < 4; ks++) {
            const int kb = ks * 16;
            unsigned af[4][4], bf[4][2];
            #pragma unroll
            for (int mi = 0; mi < 4; mi++) {
                int r = wm + mi*16 + gq;
                af[mi][0] = *(const unsigned*)&Ac[(size_t)r*RS     + kb + 2*tq    ];
                af[mi][1] = *(const unsigned*)&Ac[(size_t)(r+8)*RS + kb + 2*tq    ];
                af[mi][2] = *(const unsigned*)&Ac[(size_t)r*RS     + kb + 2*tq + 8];
                af[mi][3] = *(const unsigned*)&Ac[(size_t)(r+8)*RS + kb + 2*tq + 8];
            }
            #pragma unroll
            for (int nj = 0; nj < 4; nj++) {
                int cn = wn + nj*8 + gq;
                bf[nj][0] = *(const unsigned*)&Bc[(size_t)cn*RS + kb + 2*tq    ];
                bf[nj][1] = *(const unsigned*)&Bc[(size_t)cn*RS + kb + 2*tq + 8];
            }
            #pragma unroll
            for (int mi = 0; mi < 4; mi++)
                #pragma unroll
                for (int nj = 0; nj < 4; nj++)
                    MMA_F16(acc[mi][nj], af[mi], bf[nj]);
        }
        if (it + 1 < NITER) cp_wait0();
        __syncthreads();
    }

    // ---- epilogue: stage fp16 tile [c][r] in smem, write transposed ---------
    __half* stg = smh;   // [128 c][SST]; loop ended with __syncthreads -> safe
    #pragma unroll
    for (int mi = 0; mi < 4; mi++) {
        #pragma unroll
        for (int nj = 0; nj < 4; nj++) {
            int r  = wm + mi*16 + gq;
            int cc = wn + nj*8 + 2*tq;
            stg[(size_t)cc*SST     + r    ] = __float2half(acc[mi][nj][0]);
            stg[(size_t)(cc+1)*SST + r    ] = __float2half(acc[mi][nj][1]);
            stg[(size_t)cc*SST     + r + 8] = __float2half(acc[mi][nj][2]);
            stg[(size_t)(cc+1)*SST + r + 8] = __float2half(acc[mi][nj][3]);
        }
    }
    __syncthreads();

    // lanes own fixed row-pairs; warp w owns 16 channels
    const int R0 = bm + 2*lane;
    const int R1 = bm + 2*(lane + 32);
    const int b0i = R0 / N, t0 = R0 - b0i*N;
    const int b1i = R1 / N, t1 = R1 - b1i*N;
    #pragma unroll
    for (int i = 0; i < 16; i++) {
        int c = w*16 + i;
        unsigned v0 = *(const unsigned*)&stg[(size_t)c*SST + 2*lane];
        unsigned v1 = *(const unsigned*)&stg[(size_t)c*SST + 2*(lane+32)];
        *(unsigned*)&g_xwT[((size_t)b0i*C + bn + c)*VP + t0] = v0;
        *(unsigned*)&g_xwT[((size_t)b1i*C + bn + c)*VP + t1] = v1;
    }
}

// ---------------------------------------------------------------------------
// K4: out[b] = v[b] @ xw[b] + bias via fp16 mma.sync m16n8k16.
// Per batch: M=196 (v rows), N=768 (channels), K=196 (tokens, padded to 200).
// A = g_v16[b] [n][t] k-contig; B = g_xwT[b] [c][t] k-contig. K-tile 64, 4 iters.
// ---------------------------------------------------------------------------
__global__ __launch_bounds__(256, 2)
void gemm_out_f16(const float* __restrict__ bias,
                  float* __restrict__ OUT) {
    extern __shared__ __half smh[];
    __half* As = smh;                  // [2][128][RS]
    __half* Bs = smh + 2*128*RS;       // [2][128][RS]

    const int b = blockIdx.z;
    const __half* A  = g_v16 + (size_t)b*N*VP;
    const __half* Bm = g_xwT + (size_t)b*C*VP;
    float* O = OUT + (size_t)b*N*C;

    const int tid  = threadIdx.x;
    const int lane = tid & 31;
    const int w    = tid >> 5;
    const int wm   = (w & 1) * 64;
    const int wn   = (w >> 1) * 32;
    const int bm   = blockIdx.y * 128;     // 0 or 128
    const int bn   = blockIdx.x * 128;     // 0..640

    const int lrow = tid >> 1;
    const int lko  = (tid & 1) * 32;

    const int gq = lane >> 2;
    const int tq = lane & 3;

    float acc[4][4][4] = {};

    // prologue
    #pragma unroll
    for (int cch = 0; cch < 4; cch++) {
        int ko = lko + cch*8;
        cp16(&As[(size_t)lrow*RS + ko], &A[(size_t)(bm+lrow)*VP + ko],
             (bm + lrow < N) && (ko + 8 <= VP));
        cp16(&Bs[(size_t)lrow*RS + ko], &Bm[(size_t)(bn+lrow)*VP + ko],
             (ko + 8 <= VP));
    }
    cp_commit(); cp_wait0(); __syncthreads();

    const int NITER = 4;    // k covers 0..255; >=200 zero-filled, >=196 pads are 0
    for (int it = 0; it < NITER; it++) {
        const int cur = it & 1, nxt = cur ^ 1;
        if (it + 1 < NITER) {
            int k0 = (it + 1) * KH;
            #pragma unroll
            for (int cch = 0; cch < 4; cch++) {
                int ko = lko + cch*8;
                cp16(&As[((size_t)nxt*128 + lrow)*RS + ko],
                     &A[(size_t)(bm+lrow)*VP + k0 + ko],
                     (bm + lrow < N) && (k0 + ko + 8 <= VP));
                cp16(&Bs[((size_t)nxt*128 + lrow)*RS + ko],
                     &Bm[(size_t)(bn+lrow)*VP + k0 + ko],
                     (k0 + ko + 8 <= VP));
            }
            cp_commit();
        }

        const __half* Ac = &As[(size_t)cur*128*RS];
        const __half* Bc = &Bs[(size_t)cur*128*RS];
        #pragma unroll
        for (int ks = 0; ks < 4; ks++) {
            const int kb = ks * 16;
            unsigned af[4][4], bf[4][2];
            #pragma unroll
            for (int mi = 0; mi < 4; mi++) {
                int r = wm + mi*16 + gq;
                af[mi][0] = *(const unsigned*)&Ac[(size_t)r*RS     + kb + 2*tq    ];
                af[mi][1] = *(const unsigned*)&Ac[(size_t)(r+8)*RS + kb + 2*tq    ];
                af[mi][2] = *(const unsigned*)&Ac[(size_t)r*RS     + kb + 2*tq + 8];
                af[mi][3] = *(const unsigned*)&Ac[(size_t)(r+8)*RS + kb + 2*tq + 8];
            }
            #pragma unroll
            for (int nj = 0; nj < 4; nj++) {
                int cn = wn + nj*8 + gq;
                bf[nj][0] = *(const unsigned*)&Bc[(size_t)cn*RS + kb + 2*tq    ];
                bf[nj][1] = *(const unsigned*)&Bc[(size_t)cn*RS + kb + 2*tq + 8];
            }
            #pragma unroll
            for (int mi = 0; mi < 4; mi++)
                #pragma unroll
                for (int nj = 0; nj < 4; nj++)
                    MMA_F16(acc[mi][nj], af[mi], bf[nj]);
        }
        if (it + 1 < NITER) cp_wait0();
        __syncthreads();
    }

    // epilogue: fp32 out + bias; guard rows < 196
    #pragma unroll
    for (int mi = 0; mi < 4; mi++) {
        #pragma unroll
        for (int nj = 0; nj < 4; nj++) {
            int r  = bm + wm + mi*16 + gq;
            int cc = bn + wn + nj*8 + 2*tq;
            float b0 = bias[cc], b1 = bias[cc+1];
            if (r < N) {
                float2 lo = make_float2(acc[mi][nj][0] + b0, acc[mi][nj][1] + b1);
                *(float2*)&O[(size_t)r*C + cc] = lo;
            }
            if (r + 8 < N) {
                float2 hi = make_float2(acc[mi][nj][2] + b0, acc[mi][nj][3] + b1);
                *(float2*)&O[(size_t)(r+8)*C + cc] = hi;
            }
        }
    }
}

// ---------------------------------------------------------------------------
extern "C" void kernel_launch(void* const* d_in, const int* in_sizes, int n_in,
                              void* d_out, int out_size) {
    const float* x      = (const float*)d_in[0];   // (128,196,768)
    const float* k_c    = (const float*)d_in[1];   // (768,64)
    const float* v_c    = (const float*)d_in[2];   // (64,196,196)
    const float* proj_w = (const float*)d_in[3];   // (768,768)
    const float* proj_b = (const float*)d_in[4];   // (768,)
    float* out = (float*)d_out;

    const int SMEM_GEMM = 4*128*RS * (int)sizeof(__half);   // 73728 B
    cudaFuncSetAttribute(gemm_xw_f16,  cudaFuncAttributeMaxDynamicSharedMemorySize, SMEM_GEMM);
    cudaFuncSetAttribute(gemm_out_f16, cudaFuncAttributeMaxDynamicSharedMemorySize, SMEM_GEMM);

    pad_kernel<<<(B*N + B*C + 255)/256, 256>>>();
    split_w_kernel<<<(C*C + 255)/256, 256>>>(proj_w);
    {
        dim3 grid(B, 7);
        split_x_kernel<<<grid, 256>>>(x);
    }
    attn_kernel<<<B, 256>>>(k_c);
    {
        dim3 grid((NM + 255)/256, 4);
        mix_kernel<<<grid, 256>>>(v_c);
    }
    {
        dim3 grid(C/128, (B*N)/128);               // (6, 196)
        gemm_xw_f16<<<grid, 256, SMEM_GEMM>>>();
    }
    {
        dim3 grid(C/128, 2, B);                    // (6, 2, 128)
        gemm_out_f16<<<grid, 256, SMEM_GEMM>>>(proj_b, out);
    }
}

// round 8
// speedup vs baseline: 7.4038x; 1.0826x over previous
#include <cuda_runtime.h>
#include <cuda_fp16.h>
#include <math.h>

// Shapes (fixed by the problem)
#define B   128
#define N   196
#define C   768
#define CTR 64
#define NM  (N*N)          // 38416
#define VP  200            // padded row length (halves), 16B-aligned rows
#define KH  64             // k-tile (halves) per pipeline stage
#define RS  72             // smem row stride (halves)
#define SST 136            // epilogue staging stride (halves)

// Scratch (device globals: allocation-free rule)
__device__ float g_attn[B*CTR];
__device__ float g_qp[B*8*C];                    // partial column sums (7 used, pad 8)
__device__ __half g_xh[(size_t)B*N*C];           // fp16 x
__device__ __half g_wh[(size_t)C*C];             // fp16 proj_w [n][k]
__device__ __half g_v16[(size_t)B*N*VP];         // fp16 v, rows padded
__device__ __half g_xwT[(size_t)B*C*VP];         // fp16 xw transposed [b][c][t]

__device__ __forceinline__ void cp16(void* sdst, const void* gsrc, bool pred) {
    unsigned d = (unsigned)__cvta_generic_to_shared(sdst);
    int sz = pred ? 16 : 0;
    asm volatile("cp.async.cg.shared.global [%0], [%1], 16, %2;\n"
                 :: "r"(d), "l"(gsrc), "r"(sz));
}
__device__ __forceinline__ void cp_commit() {
    asm volatile("cp.async.commit_group;\n" ::: "memory");
}
__device__ __forceinline__ void cp_wait0() {
    asm volatile("cp.async.wait_group 0;\n" ::: "memory");
}
__device__ __forceinline__ void cp_wait1() {
    asm volatile("cp.async.wait_group 1;\n" ::: "memory");
}

#define MMA_F16(acc, af, bf)                                                  \
    asm volatile(                                                             \
        "mma.sync.aligned.m16n8k16.row.col.f32.f16.f16.f32 "                  \
        "{%0,%1,%2,%3}, {%4,%5,%6,%7}, {%8,%9}, {%0,%1,%2,%3};"               \
        : "+f"((acc)[0]), "+f"((acc)[1]), "+f"((acc)[2]), "+f"((acc)[3])      \
        : "r"((af)[0]), "r"((af)[1]), "r"((af)[2]), "r"((af)[3]),             \
          "r"((bf)[0]), "r"((bf)[1]))

// ---------------------------------------------------------------------------
// K1: fused pre-pass. grid (B, 8).
//   j in 0..6: x-chunk -> fp16 + partial column sums
//   j == 7  : proj_w -> fp16 slice, and zero row-pads of g_v16/g_xwT
// ---------------------------------------------------------------------------
__global__ void prep_kernel(const float* __restrict__ x,
                            const float* __restrict__ w) {
    const int b = blockIdx.x, j = blockIdx.y;
    const int tid = threadIdx.x;
    if (j < 7) {
        const int r0 = j * 28;
        const float* xb = x + (size_t)b*N*C;
        for (int c = tid; c < C; c += 256) {
            float s = 0.f;
            #pragma unroll 4
            for (int n = 0; n < 28; n++) {
                size_t idx = (size_t)(r0+n)*C + c;
                float v = xb[idx];
                g_xh[(size_t)b*N*C + idx] = __float2half(v);
                s += v;
            }
            g_qp[((size_t)b*8 + j)*C + c] = s;
        }
    } else {
        // proj_w slice: 4608 contiguous elements per block
        const int base = b * (C*C / B);
        for (int i = tid; i < C*C / B; i += 256)
            g_wh[base + i] = __float2half(w[base + i]);
        // pads: rows [b*964, (b+1)*964) of the NV+NX pad list
        const int NV = B * N;                   // 25088
        const int NX = B * C;                   // 98304
        const int TOT = NV + NX;                // 123392 = 964 * 128
        const int p0 = b * (TOT / B);
        for (int i = tid; i < TOT / B; i += 256) {
            int row = p0 + i;
            if (row < NV)
                *(unsigned long long*)&g_v16[(size_t)row*VP + N] = 0ull;
            else
                *(unsigned long long*)&g_xwT[(size_t)(row-NV)*VP + N] = 0ull;
        }
    }
}

// ---------------------------------------------------------------------------
// K2: finish mean, cosine-sim vs k_c (COALESCED: lane = center), softmax
// ---------------------------------------------------------------------------
__global__ void attn_kernel(const float* __restrict__ k_c) {
    const int b = blockIdx.x;
    __shared__ float q[C];
    __shared__ float red[256];
    __shared__ float sdot[4][CTR];
    __shared__ float skn[4][CTR];
    __shared__ float logits[CTR];
    const int tid = threadIdx.x;

    for (int c = tid; c < C; c += 256) {
        float s = 0.f;
        #pragma unroll
        for (int j = 0; j < 7; j++) s += g_qp[((size_t)b*8 + j)*C + c];
        q[c] = s * (1.0f/N);
    }
    __syncthreads();

    float ps = 0.f;
    for (int c = tid; c < C; c += 256) ps += q[c]*q[c];
    red[tid] = ps;
    __syncthreads();
    for (int s = 128; s > 0; s >>= 1) {
        if (tid < s) red[tid] += red[tid+s];
        __syncthreads();
    }
    const float qinv = 1.0f / fmaxf(sqrtf(red[0]), 1e-12f);

    // coalesced k_c: thread (g, c); lanes c consecutive -> 256B transactions
    {
        const int c = tid & 63, g = tid >> 6;   // g in 0..3
        float dot = 0.f, kn = 0.f;
        for (int k = g; k < C; k += 4) {
            float kv = k_c[k*CTR + c];
            dot += q[k]*kv;
            kn  += kv*kv;
        }
        sdot[g][c] = dot;
        skn[g][c]  = kn;
    }
    __syncthreads();
    if (tid < CTR) {
        float d = sdot[0][tid] + sdot[1][tid] + sdot[2][tid] + sdot[3][tid];
        float n = skn[0][tid]  + skn[1][tid]  + skn[2][tid]  + skn[3][tid];
        float kinv = 1.0f / fmaxf(sqrtf(n), 1e-12f);
        logits[tid] = d * qinv * kinv * 0.03608439182435161f; // 768^-0.5
    }
    __syncthreads();

    if (tid == 0) {
        float mx = -1e30f;
        #pragma unroll
        for (int c = 0; c < CTR; c++) mx = fmaxf(mx, logits[c]);
        float sum = 0.f;
        #pragma unroll
        for (int c = 0; c < CTR; c++) { float e = expf(logits[c]-mx); logits[c] = e; sum += e; }
        float inv = 1.0f/sum;
        #pragma unroll
        for (int c = 0; c < CTR; c++) g_attn[b*CTR + c] = logits[c]*inv;
    }
}

// ---------------------------------------------------------------------------
// K3: v[b][n][m] = sum_c attn[b,c] * v_c[c][n][m]  (fp16, padded rows)
// ---------------------------------------------------------------------------
__global__ void mix_kernel(const float* __restrict__ v_c) {
    __shared__ float a_s[32*CTR];   // 8 KB
    const int tid = threadIdx.x;
    const int g   = blockIdx.y;
    for (int i = tid; i < 32*CTR; i += 256) a_s[i] = g_attn[g*32*CTR + i];
    __syncthreads();

    const int nm = blockIdx.x*256 + tid;
    if (nm >= NM) return;
    const int n = nm / N, m = nm - n * N;

    float vr[CTR];
    #pragma unroll
    for (int c = 0; c < CTR; c++) vr[c] = v_c[(size_t)c*NM + nm];

    for (int b = 0; b < 32; b++) {
        const float* ap = a_s + b*CTR;
        float acc = 0.f;
        #pragma unroll
        for (int c = 0; c < CTR; c++) acc += ap[c]*vr[c];
        g_v16[((size_t)(g*32 + b)*N + n)*VP + m] = __float2half(acc);
    }
}

// ---------------------------------------------------------------------------
// K4: xw = x @ proj_w^T, fp16 mma m16n8k16, 3-STAGE cp.async ring.
// M=25088, N=768, K=768. Block 128x128, K-tile 64, warp tile 64x32.
// Output written TRANSPOSED to g_xwT[b][c][t] via smem-staged epilogue.
// ---------------------------------------------------------------------------
__global__ __launch_bounds__(256, 2)
void gemm_xw_f16() {
    extern __shared__ __half smh[];
    // stage s: A at smh + s*2*128*RS, B at +128*RS
    const int tid  = threadIdx.x;
    const int lane = tid & 31;
    const int w    = tid >> 5;
    const int wm   = (w & 1) * 64;
    const int wn   = (w >> 1) * 32;
    const int bm   = blockIdx.y * 128;
    const int bn   = blockIdx.x * 128;

    const int lrow = tid >> 1;
    const int lko  = (tid & 1) * 32;

    const int gq = lane >> 2;
    const int tq = lane & 3;

    float acc[4][4][4] = {};

    auto issue_load = [&](int s, int k0) {
        __half* As = smh + (size_t)s*2*128*RS;
        __half* Bs = As + (size_t)128*RS;
        #pragma unroll
        for (int cch = 0; cch < 4; cch++) {
            int ko = lko + cch*8;
            cp16(&As[(size_t)lrow*RS + ko], &g_xh[(size_t)(bm+lrow)*C + k0 + ko], true);
            cp16(&Bs[(size_t)lrow*RS + ko], &g_wh[(size_t)(bn+lrow)*C + k0 + ko], true);
        }
        cp_commit();
    };

    const int NITER = C / KH;   // 12
    issue_load(0, 0);
    issue_load(1, KH);

    for (int it = 0; it < NITER; it++) {
        const int cur = it % 3;
        if (it + 2 < NITER) cp_wait1(); else if (it + 1 < NITER) cp_wait0();
        else cp_wait0();
        __syncthreads();
        if (it + 2 < NITER) issue_load((it + 2) % 3, (it + 2) * KH);

        const __half* Ac = smh + (size_t)cur*2*128*RS;
        const __half* Bc = Ac + (size_t)128*RS;
        #pragma unroll
        for (int ks = 0; ks < 4; ks++) {
            const int kb = ks * 16;
            unsigned af[4][4], bf[4][2];
            #pragma unroll
            for (int mi = 0; mi < 4; mi++) {
                int r = wm + mi*16 + gq;
                af[mi][0] = *(const unsigned*)&Ac[(size_t)r*RS     + kb + 2*tq    ];
                af[mi][1] = *(const unsigned*)&Ac[(size_t)(r+8)*RS + kb + 2*tq    ];
                af[mi][2] = *(const unsigned*)&Ac[(size_t)r*RS     + kb + 2*tq + 8];
                af[mi][3] = *(const unsigned*)&Ac[(size_t)(r+8)*RS + kb + 2*tq + 8];
            }
            #pragma unroll
            for (int nj = 0; nj < 4; nj++) {
                int cn = wn + nj*8 + gq;
                bf[nj][0] = *(const unsigned*)&Bc[(size_t)cn*RS + kb + 2*tq    ];
                bf[nj][1] = *(const unsigned*)&Bc[(size_t)cn*RS + kb + 2*tq + 8];
            }
            #pragma unroll
            for (int mi = 0; mi < 4; mi++)
                #pragma unroll
                for (int nj = 0; nj < 4; nj++)
                    MMA_F16(acc[mi][nj], af[mi], bf[nj]);
        }
    }
    __syncthreads();

    // epilogue: stage fp16 tile [c][r] in smem, write transposed
    __half* stg = smh;
    #pragma unroll
    for (int mi = 0; mi < 4; mi++) {
        #pragma unroll
        for (int nj = 0; nj < 4; nj++) {
            int r  = wm + mi*16 + gq;
            int cc = wn + nj*8 + 2*tq;
            stg[(size_t)cc*SST     + r    ] = __float2half(acc[mi][nj][0]);
            stg[(size_t)(cc+1)*SST + r    ] = __float2half(acc[mi][nj][1]);
            stg[(size_t)cc*SST     + r + 8] = __float2half(acc[mi][nj][2]);
            stg[(size_t)(cc+1)*SST + r + 8] = __float2half(acc[mi][nj][3]);
        }
    }
    __syncthreads();

    const int R0 = bm + 2*lane;
    const int R1 = bm + 2*(lane + 32);
    const int b0i = R0 / N, t0 = R0 - b0i*N;
    const int b1i = R1 / N, t1 = R1 - b1i*N;
    #pragma unroll
    for (int i = 0; i < 16; i++) {
        int c = w*16 + i;
        unsigned v0 = *(const unsigned*)&stg[(size_t)c*SST + 2*lane];
        unsigned v1 = *(const unsigned*)&stg[(size_t)c*SST + 2*(lane+32)];
        *(unsigned*)&g_xwT[((size_t)b0i*C + bn + c)*VP + t0] = v0;
        *(unsigned*)&g_xwT[((size_t)b1i*C + bn + c)*VP + t1] = v1;
    }
}

// ---------------------------------------------------------------------------
// K5: out[b] = v[b] @ xw[b] + bias, fp16 mma m16n8k16, 2-stage cp.async.
// Per batch: M=196, N=768, K=196 (padded 200; k>=196 terms are 0*0).
// ---------------------------------------------------------------------------
__global__ __launch_bounds__(256, 2)
void gemm_out_f16(const float* __restrict__ bias,
                  float* __restrict__ OUT) {
    extern __shared__ __half smh[];
    __half* As = smh;                  // [2][128][RS]
    __half* Bs = smh + 2*128*RS;       // [2][128][RS]

    const int b = blockIdx.z;
    const __half* A  = g_v16 + (size_t)b*N*VP;
    const __half* Bm = g_xwT + (size_t)b*C*VP;
    float* O = OUT + (size_t)b*N*C;

    const int tid  = threadIdx.x;
    const int lane = tid & 31;
    const int w    = tid >> 5;
    const int wm   = (w & 1) * 64;
    const int wn   = (w >> 1) * 32;
    const int bm   = blockIdx.y * 128;
    const int bn   = blockIdx.x * 128;

    const int lrow = tid >> 1;
    const int lko  = (tid & 1) * 32;

    const int gq = lane >> 2;
    const int tq = lane & 3;

    float acc[4][4][4] = {};

    #pragma unroll
    for (int cch = 0; cch < 4; cch++) {
        int ko = lko + cch*8;
        cp16(&As[(size_t)lrow*RS + ko], &A[(size_t)(bm+lrow)*VP + ko],
             (bm + lrow < N) && (ko + 8 <= VP));
        cp16(&Bs[(size_t)lrow*RS + ko], &Bm[(size_t)(bn+lrow)*VP + ko],
             (ko + 8 <= VP));
    }
    cp_commit(); cp_wait0(); __syncthreads();

    const int NITER = 4;
    for (int it = 0; it < NITER; it++) {
        const int cur = it & 1, nxt = cur ^ 1;
        if (it + 1 < NITER) {
            int k0 = (it + 1) * KH;
            #pragma unroll
            for (int cch = 0; cch < 4; cch++) {
                int ko = lko + cch*8;
                cp16(&As[((size_t)nxt*128 + lrow)*RS + ko],
                     &A[(size_t)(bm+lrow)*VP + k0 + ko],
                     (bm + lrow < N) && (k0 + ko + 8 <= VP));
                cp16(&Bs[((size_t)nxt*128 + lrow)*RS + ko],
                     &Bm[(size_t)(bn+lrow)*VP + k0 + ko],
                     (k0 + ko + 8 <= VP));
            }
            cp_commit();
        }

        const __half* Ac = &As[(size_t)cur*128*RS];
        const __half* Bc = &Bs[(size_t)cur*128*RS];
        #pragma unroll
        for (int ks = 0; ks < 4; ks++) {
            const int kb = ks * 16;
            unsigned af[4][4], bf[4][2];
            #pragma unroll
            for (int mi = 0; mi < 4; mi++) {
                int r = wm + mi*16 + gq;
                af[mi][0] = *(const unsigned*)&Ac[(size_t)r*RS     + kb + 2*tq    ];
                af[mi][1] = *(const unsigned*)&Ac[(size_t)(r+8)*RS + kb + 2*tq    ];
                af[mi][2] = *(const unsigned*)&Ac[(size_t)r*RS     + kb + 2*tq + 8];
                af[mi][3] = *(const unsigned*)&Ac[(size_t)(r+8)*RS + kb + 2*tq + 8];
            }
            #pragma unroll
            for (int nj = 0; nj < 4; nj++) {
                int cn = wn + nj*8 + gq;
                bf[nj][0] = *(const unsigned*)&Bc[(size_t)cn*RS + kb + 2*tq    ];
                bf[nj][1] = *(const unsigned*)&Bc[(size_t)cn*RS + kb + 2*tq + 8];
            }
            #pragma unroll
            for (int mi = 0; mi < 4; mi++)
                #pragma unroll
                for (int nj = 0; nj < 4; nj++)
                    MMA_F16(acc[mi][nj], af[mi], bf[nj]);
        }
        if (it + 1 < NITER) cp_wait0();
        __syncthreads();
    }

    #pragma unroll
    for (int mi = 0; mi < 4; mi++) {
        #pragma unroll
        for (int nj = 0; nj < 4; nj++) {
            int r  = bm + wm + mi*16 + gq;
            int cc = bn + wn + nj*8 + 2*tq;
            float b0 = bias[cc], b1 = bias[cc+1];
            if (r < N) {
                float2 lo = make_float2(acc[mi][nj][0] + b0, acc[mi][nj][1] + b1);
                *(float2*)&O[(size_t)r*C + cc] = lo;
            }
            if (r + 8 < N) {
                float2 hi = make_float2(acc[mi][nj][2] + b0, acc[mi][nj][3] + b1);
                *(float2*)&O[(size_t)(r+8)*C + cc] = hi;
            }
        }
    }
}

// ---------------------------------------------------------------------------
extern "C" void kernel_launch(void* const* d_in, const int* in_sizes, int n_in,
                              void* d_out, int out_size) {
    const float* x      = (const float*)d_in[0];   // (128,196,768)
    const float* k_c    = (const float*)d_in[1];   // (768,64)
    const float* v_c    = (const float*)d_in[2];   // (64,196,196)
    const float* proj_w = (const float*)d_in[3];   // (768,768)
    const float* proj_b = (const float*)d_in[4];   // (768,)
    float* out = (float*)d_out;

    const int SMEM_XW  = 3*2*128*RS * (int)sizeof(__half);  // 110592
    const int SMEM_OUT = 4*128*RS * (int)sizeof(__half);    // 73728
    cudaFuncSetAttribute(gemm_xw_f16,  cudaFuncAttributeMaxDynamicSharedMemorySize, SMEM_XW);
    cudaFuncSetAttribute(gemm_out_f16, cudaFuncAttributeMaxDynamicSharedMemorySize, SMEM_OUT);

    {
        dim3 grid(B, 8);
        prep_kernel<<<grid, 256>>>(x, proj_w);     // launch 1
    }
    attn_kernel<<<B, 256>>>(k_c);                  // launch 2
    {
        dim3 grid((NM + 255)/256, 4);
        mix_kernel<<<grid, 256>>>(v_c);            // launch 3
    }
    {
        dim3 grid(C/128, (B*N)/128);               // (6, 196)
        gemm_xw_f16<<<grid, 256, SMEM_XW>>>();     // launch 4 (profiled)
    }
    {
        dim3 grid(C/128, 2, B);                    // (6, 2, 128)
        gemm_out_f16<<<grid, 256, SMEM_OUT>>>(proj_b, out);
    }
}

// round 9
// speedup vs baseline: 7.7553x; 1.0475x over previous
#include <cuda_runtime.h>
#include <cuda_fp16.h>
#include <math.h>

// Shapes (fixed by the problem)
#define B   128
#define N   196
#define C   768
#define CTR 64
#define NM  (N*N)          // 38416
#define VP  200            // padded row length (halves), 16B-aligned rows
#define KH  64             // k-tile (halves) per pipeline stage
#define RS  72             // smem row stride (halves); 144B rows -> ldmatrix conflict-free
#define SST 136            // epilogue staging stride (halves)

// Scratch (device globals: allocation-free rule)
__device__ float g_attn[B*CTR];
__device__ float g_qp[B*8*C];                    // partial column sums (7 used, pad 8)
__device__ __half g_xh[(size_t)B*N*C];           // fp16 x
__device__ __half g_wh[(size_t)C*C];             // fp16 proj_w [n][k]
__device__ __half g_v16[(size_t)B*N*VP];         // fp16 v, rows padded
__device__ __half g_xwT[(size_t)B*C*VP];         // fp16 xw transposed [b][c][t]

__device__ __forceinline__ void cp16(void* sdst, const void* gsrc, bool pred) {
    unsigned d = (unsigned)__cvta_generic_to_shared(sdst);
    int sz = pred ? 16 : 0;
    asm volatile("cp.async.cg.shared.global [%0], [%1], 16, %2;\n"
                 :: "r"(d), "l"(gsrc), "r"(sz));
}
__device__ __forceinline__ void cp_commit() {
    asm volatile("cp.async.commit_group;\n" ::: "memory");
}
__device__ __forceinline__ void cp_wait0() {
    asm volatile("cp.async.wait_group 0;\n" ::: "memory");
}
__device__ __forceinline__ void cp_wait1() {
    asm volatile("cp.async.wait_group 1;\n" ::: "memory");
}

#define MMA_F16(acc, af, bf)                                                  \
    asm volatile(                                                             \
        "mma.sync.aligned.m16n8k16.row.col.f32.f16.f16.f32 "                  \
        "{%0,%1,%2,%3}, {%4,%5,%6,%7}, {%8,%9}, {%0,%1,%2,%3};"               \
        : "+f"((acc)[0]), "+f"((acc)[1]), "+f"((acc)[2]), "+f"((acc)[3])      \
        : "r"((af)[0]), "r"((af)[1]), "r"((af)[2]), "r"((af)[3]),             \
          "r"((bf)[0]), "r"((bf)[1]))

#define LDM_X4(r0, r1, r2, r3, addr)                                          \
    asm volatile(                                                             \
        "ldmatrix.sync.aligned.m8n8.x4.shared.b16 {%0,%1,%2,%3}, [%4];"       \
        : "=r"(r0), "=r"(r1), "=r"(r2), "=r"(r3) : "r"(addr))

// ---------------------------------------------------------------------------
// K1: fused pre-pass. grid (B, 8).
// ---------------------------------------------------------------------------
__global__ void prep_kernel(const float* __restrict__ x,
                            const float* __restrict__ w) {
    const int b = blockIdx.x, j = blockIdx.y;
    const int tid = threadIdx.x;
    if (j < 7) {
        const int r0 = j * 28;
        const float* xb = x + (size_t)b*N*C;
        for (int c = tid; c < C; c += 256) {
            float s = 0.f;
            #pragma unroll 4
            for (int n = 0; n < 28; n++) {
                size_t idx = (size_t)(r0+n)*C + c;
                float v = xb[idx];
                g_xh[(size_t)b*N*C + idx] = __float2half(v);
                s += v;
            }
            g_qp[((size_t)b*8 + j)*C + c] = s;
        }
    } else {
        const int base = b * (C*C / B);
        for (int i = tid; i < C*C / B; i += 256)
            g_wh[base + i] = __float2half(w[base + i]);
        const int NV = B * N;
        const int NX = B * C;
        const int TOT = NV + NX;                // 123392 = 964 * 128
        const int p0 = b * (TOT / B);
        for (int i = tid; i < TOT / B; i += 256) {
            int row = p0 + i;
            if (row < NV)
                *(unsigned long long*)&g_v16[(size_t)row*VP + N] = 0ull;
            else
                *(unsigned long long*)&g_xwT[(size_t)(row-NV)*VP + N] = 0ull;
        }
    }
}

// ---------------------------------------------------------------------------
// K2: finish mean, cosine-sim vs k_c (coalesced), softmax
// ---------------------------------------------------------------------------
__global__ void attn_kernel(const float* __restrict__ k_c) {
    const int b = blockIdx.x;
    __shared__ float q[C];
    __shared__ float red[256];
    __shared__ float sdot[4][CTR];
    __shared__ float skn[4][CTR];
    __shared__ float logits[CTR];
    const int tid = threadIdx.x;

    for (int c = tid; c < C; c += 256) {
        float s = 0.f;
        #pragma unroll
        for (int j = 0; j < 7; j++) s += g_qp[((size_t)b*8 + j)*C + c];
        q[c] = s * (1.0f/N);
    }
    __syncthreads();

    float ps = 0.f;
    for (int c = tid; c < C; c += 256) ps += q[c]*q[c];
    red[tid] = ps;
    __syncthreads();
    for (int s = 128; s > 0; s >>= 1) {
        if (tid < s) red[tid] += red[tid+s];
        __syncthreads();
    }
    const float qinv = 1.0f / fmaxf(sqrtf(red[0]), 1e-12f);

    {
        const int c = tid & 63, g = tid >> 6;
        float dot = 0.f, kn = 0.f;
        for (int k = g; k < C; k += 4) {
            float kv = k_c[k*CTR + c];
            dot += q[k]*kv;
            kn  += kv*kv;
        }
        sdot[g][c] = dot;
        skn[g][c]  = kn;
    }
    __syncthreads();
    if (tid < CTR) {
        float d = sdot[0][tid] + sdot[1][tid] + sdot[2][tid] + sdot[3][tid];
        float n = skn[0][tid]  + skn[1][tid]  + skn[2][tid]  + skn[3][tid];
        float kinv = 1.0f / fmaxf(sqrtf(n), 1e-12f);
        logits[tid] = d * qinv * kinv * 0.03608439182435161f;
    }
    __syncthreads();

    if (tid == 0) {
        float mx = -1e30f;
        #pragma unroll
        for (int c = 0; c < CTR; c++) mx = fmaxf(mx, logits[c]);
        float sum = 0.f;
        #pragma unroll
        for (int c = 0; c < CTR; c++) { float e = expf(logits[c]-mx); logits[c] = e; sum += e; }
        float inv = 1.0f/sum;
        #pragma unroll
        for (int c = 0; c < CTR; c++) g_attn[b*CTR + c] = logits[c]*inv;
    }
}

// ---------------------------------------------------------------------------
// K3: v[b][n][m] = sum_c attn[b,c] * v_c[c][n][m]  (fp16, padded rows)
// ---------------------------------------------------------------------------
__global__ void mix_kernel(const float* __restrict__ v_c) {
    __shared__ float a_s[32*CTR];
    const int tid = threadIdx.x;
    const int g   = blockIdx.y;
    for (int i = tid; i < 32*CTR; i += 256) a_s[i] = g_attn[g*32*CTR + i];
    __syncthreads();

    const int nm = blockIdx.x*256 + tid;
    if (nm >= NM) return;
    const int n = nm / N, m = nm - n * N;

    float vr[CTR];
    #pragma unroll
    for (int c = 0; c < CTR; c++) vr[c] = v_c[(size_t)c*NM + nm];

    for (int b = 0; b < 32; b++) {
        const float* ap = a_s + b*CTR;
        float acc = 0.f;
        #pragma unroll
        for (int c = 0; c < CTR; c++) acc += ap[c]*vr[c];
        g_v16[((size_t)(g*32 + b)*N + n)*VP + m] = __float2half(acc);
    }
}

// ---------------------------------------------------------------------------
// K4: xw = x @ proj_w^T, fp16 mma m16n8k16 + ldmatrix, 3-stage cp.async ring.
// ---------------------------------------------------------------------------
__global__ __launch_bounds__(256, 2)
void gemm_xw_f16() {
    extern __shared__ __half smh[];
    const int tid  = threadIdx.x;
    const int lane = tid & 31;
    const int w    = tid >> 5;
    const int wm   = (w & 1) * 64;
    const int wn   = (w >> 1) * 32;
    const int bm   = blockIdx.y * 128;
    const int bn   = blockIdx.x * 128;

    const int lrow = tid >> 1;
    const int lko  = (tid & 1) * 32;

    const int gq = lane >> 2;
    const int tq = lane & 3;

    // ldmatrix per-lane row/col assignments
    const int aRow = wm + (lane & 7) + ((lane >> 3) & 1) * 8;  // + mi*16
    const int aK   = (lane >> 4) * 8;                          // + kb
    const int bN   = wn + (lane & 7) + (lane >> 4) * 8;        // + njpair*16
    const int bK   = ((lane >> 3) & 1) * 8;                    // + kb

    float acc[4][4][4] = {};

    auto issue_load = [&](int s, int k0) {
        __half* As = smh + (size_t)s*2*128*RS;
        __half* Bs = As + (size_t)128*RS;
        #pragma unroll
        for (int cch = 0; cch < 4; cch++) {
            int ko = lko + cch*8;
            cp16(&As[(size_t)lrow*RS + ko], &g_xh[(size_t)(bm+lrow)*C + k0 + ko], true);
            cp16(&Bs[(size_t)lrow*RS + ko], &g_wh[(size_t)(bn+lrow)*C + k0 + ko], true);
        }
        cp_commit();
    };

    const int NITER = C / KH;   // 12
    issue_load(0, 0);
    issue_load(1, KH);

    for (int it = 0; it < NITER; it++) {
        const int cur = it % 3;
        if (it + 2 < NITER) cp_wait1(); else cp_wait0();
        __syncthreads();
        if (it + 2 < NITER) issue_load((it + 2) % 3, (it + 2) * KH);

        const __half* Ac = smh + (size_t)cur*2*128*RS;
        const __half* Bc = Ac + (size_t)128*RS;
        const unsigned Acs = (unsigned)__cvta_generic_to_shared(Ac);
        const unsigned Bcs = (unsigned)__cvta_generic_to_shared(Bc);
        #pragma unroll
        for (int ks = 0; ks < 4; ks++) {
            const int kb = ks * 16;
            unsigned af[4][4], bf[4][2];
            #pragma unroll
            for (int mi = 0; mi < 4; mi++)
                LDM_X4(af[mi][0], af[mi][1], af[mi][2], af[mi][3],
                       Acs + (unsigned)(((aRow + mi*16)*RS + kb + aK) * 2));
            LDM_X4(bf[0][0], bf[0][1], bf[1][0], bf[1][1],
                   Bcs + (unsigned)((bN*RS + kb + bK) * 2));
            LDM_X4(bf[2][0], bf[2][1], bf[3][0], bf[3][1],
                   Bcs + (unsigned)(((bN + 16)*RS + kb + bK) * 2));
            #pragma unroll
            for (int mi = 0; mi < 4; mi++)
                #pragma unroll
                for (int nj = 0; nj < 4; nj++)
                    MMA_F16(acc[mi][nj], af[mi], bf[nj]);
        }
    }
    __syncthreads();

    // epilogue: stage fp16 tile [c][r] in smem, write transposed
    __half* stg = smh;
    #pragma unroll
    for (int mi = 0; mi < 4; mi++) {
        #pragma unroll
        for (int nj = 0; nj < 4; nj++) {
            int r  = wm + mi*16 + gq;
            int cc = wn + nj*8 + 2*tq;
            stg[(size_t)cc*SST     + r    ] = __float2half(acc[mi][nj][0]);
            stg[(size_t)(cc+1)*SST + r    ] = __float2half(acc[mi][nj][1]);
            stg[(size_t)cc*SST     + r + 8] = __float2half(acc[mi][nj][2]);
            stg[(size_t)(cc+1)*SST + r + 8] = __float2half(acc[mi][nj][3]);
        }
    }
    __syncthreads();

    const int R0 = bm + 2*lane;
    const int R1 = bm + 2*(lane + 32);
    const int b0i = R0 / N, t0 = R0 - b0i*N;
    const int b1i = R1 / N, t1 = R1 - b1i*N;
    #pragma unroll
    for (int i = 0; i < 16; i++) {
        int c = w*16 + i;
        unsigned v0 = *(const unsigned*)&stg[(size_t)c*SST + 2*lane];
        unsigned v1 = *(const unsigned*)&stg[(size_t)c*SST + 2*(lane+32)];
        *(unsigned*)&g_xwT[((size_t)b0i*C + bn + c)*VP + t0] = v0;
        *(unsigned*)&g_xwT[((size_t)b1i*C + bn + c)*VP + t1] = v1;
    }
}

// ---------------------------------------------------------------------------
// K5: out[b] = v[b] @ xw[b] + bias, fp16 mma m16n8k16 + ldmatrix, 2-stage.
// ---------------------------------------------------------------------------
__global__ __launch_bounds__(256, 2)
void gemm_out_f16(const float* __restrict__ bias,
                  float* __restrict__ OUT) {
    extern __shared__ __half smh[];
    __half* As = smh;                  // [2][128][RS]
    __half* Bs = smh + 2*128*RS;       // [2][128][RS]

    const int b = blockIdx.z;
    const __half* A  = g_v16 + (size_t)b*N*VP;
    const __half* Bm = g_xwT + (size_t)b*C*VP;
    float* O = OUT + (size_t)b*N*C;

    const int tid  = threadIdx.x;
    const int lane = tid & 31;
    const int w    = tid >> 5;
    const int wm   = (w & 1) * 64;
    const int wn   = (w >> 1) * 32;
    const int bm   = blockIdx.y * 128;
    const int bn   = blockIdx.x * 128;

    const int lrow = tid >> 1;
    const int lko  = (tid & 1) * 32;

    const int gq = lane >> 2;
    const int tq = lane & 3;

    const int aRow = wm + (lane & 7) + ((lane >> 3) & 1) * 8;
    const int aK   = (lane >> 4) * 8;
    const int bN   = wn + (lane & 7) + (lane >> 4) * 8;
    const int bK   = ((lane >> 3) & 1) * 8;

    float acc[4][4][4] = {};

    #pragma unroll
    for (int cch = 0; cch < 4; cch++) {
        int ko = lko + cch*8;
        cp16(&As[(size_t)lrow*RS + ko], &A[(size_t)(bm+lrow)*VP + ko],
             (bm + lrow < N) && (ko + 8 <= VP));
        cp16(&Bs[(size_t)lrow*RS + ko], &Bm[(size_t)(bn+lrow)*VP + ko],
             (ko + 8 <= VP));
    }
    cp_commit(); cp_wait0(); __syncthreads();

    const int NITER = 4;
    for (int it = 0; it < NITER; it++) {
        const int cur = it & 1, nxt = cur ^ 1;
        if (it + 1 < NITER) {
            int k0 = (it + 1) * KH;
            #pragma unroll
            for (int cch = 0; cch < 4; cch++) {
                int ko = lko + cch*8;
                cp16(&As[((size_t)nxt*128 + lrow)*RS + ko],
                     &A[(size_t)(bm+lrow)*VP + k0 + ko],
                     (bm + lrow < N) && (k0 + ko + 8 <= VP));
                cp16(&Bs[((size_t)nxt*128 + lrow)*RS + ko],
                     &Bm[(size_t)(bn+lrow)*VP + k0 + ko],
                     (k0 + ko + 8 <= VP));
            }
            cp_commit();
        }

        const __half* Ac = &As[(size_t)cur*128*RS];
        const __half* Bc = &Bs[(size_t)cur*128*RS];
        const unsigned Acs = (unsigned)__cvta_generic_to_shared(Ac);
        const unsigned Bcs = (unsigned)__cvta_generic_to_shared(Bc);
        #pragma unroll
        for (int ks = 0; ks < 4; ks++) {
            const int kb = ks * 16;
            unsigned af[4][4], bf[4][2];
            #pragma unroll
            for (int mi = 0; mi < 4; mi++)
                LDM_X4(af[mi][0], af[mi][1], af[mi][2], af[mi][3],
                       Acs + (unsigned)(((aRow + mi*16)*RS + kb + aK) * 2));
            LDM_X4(bf[0][0], bf[0][1], bf[1][0], bf[1][1],
                   Bcs + (unsigned)((bN*RS + kb + bK) * 2));
            LDM_X4(bf[2][0], bf[2][1], bf[3][0], bf[3][1],
                   Bcs + (unsigned)(((bN + 16)*RS + kb + bK) * 2));
            #pragma unroll
            for (int mi = 0; mi < 4; mi++)
                #pragma unroll
                for (int nj = 0; nj < 4; nj++)
                    MMA_F16(acc[mi][nj], af[mi], bf[nj]);
        }
        if (it + 1 < NITER) cp_wait0();
        __syncthreads();
    }

    #pragma unroll
    for (int mi = 0; mi < 4; mi++) {
        #pragma unroll
        for (int nj = 0; nj < 4; nj++) {
            int r  = bm + wm + mi*16 + gq;
            int cc = bn + wn + nj*8 + 2*tq;
            float b0 = bias[cc], b1 = bias[cc+1];
            if (r < N) {
                float2 lo = make_float2(acc[mi][nj][0] + b0, acc[mi][nj][1] + b1);
                *(float2*)&O[(size_t)r*C + cc] = lo;
            }
            if (r + 8 < N) {
                float2 hi = make_float2(acc[mi][nj][2] + b0, acc[mi][nj][3] + b1);
                *(float2*)&O[(size_t)(r+8)*C + cc] = hi;
            }
        }
    }
}

// ---------------------------------------------------------------------------
extern "C" void kernel_launch(void* const* d_in, const int* in_sizes, int n_in,
                              void* d_out, int out_size) {
    const float* x      = (const float*)d_in[0];   // (128,196,768)
    const float* k_c    = (const float*)d_in[1];   // (768,64)
    const float* v_c    = (const float*)d_in[2];   // (64,196,196)
    const float* proj_w = (const float*)d_in[3];   // (768,768)
    const float* proj_b = (const float*)d_in[4];   // (768,)
    float* out = (float*)d_out;

    const int SMEM_XW  = 3*2*128*RS * (int)sizeof(__half);  // 110592
    const int SMEM_OUT = 4*128*RS * (int)sizeof(__half);    // 73728
    cudaFuncSetAttribute(gemm_xw_f16,  cudaFuncAttributeMaxDynamicSharedMemorySize, SMEM_XW);
    cudaFuncSetAttribute(gemm_out_f16, cudaFuncAttributeMaxDynamicSharedMemorySize, SMEM_OUT);

    {
        dim3 grid(B, 8);
        prep_kernel<<<grid, 256>>>(x, proj_w);     // launch 1
    }
    attn_kernel<<<B, 256>>>(k_c);                  // launch 2
    {
        dim3 grid((NM + 255)/256, 4);
        mix_kernel<<<grid, 256>>>(v_c);            // launch 3
    }
    {
        dim3 grid(C/128, (B*N)/128);               // (6, 196)
        gemm_xw_f16<<<grid, 256, SMEM_XW>>>();     // launch 4 (profiled)
    }
    {
        dim3 grid(C/128, 2, B);                    // (6, 2, 128)
        gemm_out_f16<<<grid, 256, SMEM_OUT>>>(proj_b, out);
    }
}